// round 1
// baseline (speedup 1.0000x reference)
#include <cuda_runtime.h>
#include <math.h>

// ---------------- constants ----------------
namespace {
constexpr int Bb = 8, Hh = 64, Ww = 64, Cc = 768;
constexpr int NH = 12, HD = 64, WS = 14, MLP = 3072;
constexpr float EPS = 1e-6f;
constexpr float SCALE = 0.125f;              // 64^-0.5
constexpr int NWH = 5, NWW = 5;              // 70/14 windows per dim
constexpr int NWIN = Bb * NWH * NWW;         // 200
constexpr int NTOK = WS * WS;                // 196
constexpr int M1 = NWIN * NTOK;              // 39200 (window tokens)
constexpr int M2 = Bb * Hh * Ww;             // 32768 (image tokens)
constexpr int NREL = 2 * WS - 1;             // 27
}

// ---------------- scratch (device globals; no allocation allowed) ----------------
__device__ float g_xln[(size_t)M1 * Cc];              // LN1 output, window layout
__device__ float g_q[(size_t)NWIN * NH * NTOK * HD];  // head-major
__device__ float g_k[(size_t)NWIN * NH * NTOK * HD];
__device__ float g_v[(size_t)NWIN * NH * NTOK * HD];
__device__ float g_attnout[(size_t)M1 * Cc];          // attention output (window layout, C cols)
__device__ float g_h[(size_t)M2 * Cc];                // residual + attn (image layout)
__device__ float g_x2[(size_t)M2 * Cc];               // LN2 output
__device__ float g_m1[(size_t)M2 * MLP];              // MLP hidden

// ---------------- layernorm core (256 threads, C=768 -> 3/thread) ----------------
__device__ __forceinline__ void ln_compute(const float* __restrict__ xr,
                                           const float* __restrict__ g,
                                           const float* __restrict__ bsh,
                                           float* __restrict__ o) {
  float vals[3];
  float s = 0.f, s2 = 0.f;
#pragma unroll
  for (int t = 0; t < 3; t++) {
    float v = xr[threadIdx.x + t * 256];
    vals[t] = v; s += v; s2 += v * v;
  }
#pragma unroll
  for (int off = 16; off > 0; off >>= 1) {
    s  += __shfl_down_sync(0xffffffffu, s, off);
    s2 += __shfl_down_sync(0xffffffffu, s2, off);
  }
  __shared__ float rs[8], rq[8];
  __shared__ float s_mu, s_inv;
  int lane = threadIdx.x & 31, warp = threadIdx.x >> 5;
  if (lane == 0) { rs[warp] = s; rq[warp] = s2; }
  __syncthreads();
  if (threadIdx.x == 0) {
    float a = 0.f, b2 = 0.f;
#pragma unroll
    for (int i = 0; i < 8; i++) { a += rs[i]; b2 += rq[i]; }
    float mu = a * (1.f / 768.f);
    float var = b2 * (1.f / 768.f) - mu * mu;
    s_mu = mu; s_inv = rsqrtf(var + EPS);
  }
  __syncthreads();
  float mu = s_mu, inv = s_inv;
#pragma unroll
  for (int t = 0; t < 3; t++) {
    int c = threadIdx.x + t * 256;
    o[c] = (vals[t] - mu) * inv * g[c] + bsh[c];
  }
}

// LN1 fused with window partition (+ zero padding rows)
__global__ __launch_bounds__(256) void k_ln1(const float* __restrict__ x,
                                             const float* __restrict__ g,
                                             const float* __restrict__ b) {
  int m = blockIdx.x;
  int win = m / NTOK, tok = m - win * NTOK;
  int bb = win / 25, wr = win % 25, wh = wr / 5, ww = wr % 5;
  int i = tok / WS, j = tok - i * WS;
  int h = wh * WS + i, w = ww * WS + j;
  float* o = g_xln + (size_t)m * Cc;
  if (h >= Hh || w >= Ww) {
    for (int c = threadIdx.x; c < Cc; c += 256) o[c] = 0.f;
    return;
  }
  const float* xr = x + (((size_t)bb * Hh + h) * Ww + w) * Cc;
  ln_compute(xr, g, b, o);
}

__global__ __launch_bounds__(256) void k_ln2(const float* __restrict__ g,
                                             const float* __restrict__ b) {
  int m = blockIdx.x;
  ln_compute(g_h + (size_t)m * Cc, g, b, g_x2 + (size_t)m * Cc);
}

// ---------------- tiled fp32 GEMM with fused epilogues ----------------
constexpr int BM = 128, BN = 128, BK = 8;
enum { EPI_QKV = 0, EPI_PROJ = 1, EPI_LIN1 = 2, EPI_LIN2 = 3 };

template <int EPI>
__global__ __launch_bounds__(256) void k_gemm(const float* __restrict__ Bw,
                                              const float* __restrict__ bias,
                                              float* __restrict__ Cout,
                                              const float* __restrict__ extra,
                                              int M, int N, int K) {
  const float* __restrict__ A =
      (EPI == EPI_QKV) ? g_xln : (EPI == EPI_PROJ) ? g_attnout
                              : (EPI == EPI_LIN1) ? g_x2 : g_m1;

  __shared__ float As[BK][BM];
  __shared__ float Bs[BK][BN];

  int tid = threadIdx.x;
  int row0 = blockIdx.y * BM, col0 = blockIdx.x * BN;
  int arow = tid >> 1, ak = (tid & 1) * 4;
  int brow = tid >> 5, bcol = (tid & 31) * 4;
  int tx = tid & 15, ty = tid >> 4;

  float acc[8][8];
#pragma unroll
  for (int i = 0; i < 8; i++)
#pragma unroll
    for (int j = 0; j < 8; j++) acc[i][j] = 0.f;

  for (int k0 = 0; k0 < K; k0 += BK) {
    float4 av;
    int gm = row0 + arow;
    if (gm < M) av = *(const float4*)(A + (size_t)gm * K + k0 + ak);
    else av = make_float4(0.f, 0.f, 0.f, 0.f);
    As[ak + 0][arow] = av.x; As[ak + 1][arow] = av.y;
    As[ak + 2][arow] = av.z; As[ak + 3][arow] = av.w;
    *(float4*)&Bs[brow][bcol] =
        *(const float4*)(Bw + (size_t)(k0 + brow) * N + col0 + bcol);
    __syncthreads();
#pragma unroll
    for (int kk = 0; kk < BK; kk++) {
      float a[8], bv[8];
      *(float4*)&a[0] = *(const float4*)&As[kk][ty * 8];
      *(float4*)&a[4] = *(const float4*)&As[kk][ty * 8 + 4];
      *(float4*)&bv[0] = *(const float4*)&Bs[kk][tx * 8];
      *(float4*)&bv[4] = *(const float4*)&Bs[kk][tx * 8 + 4];
#pragma unroll
      for (int i = 0; i < 8; i++)
#pragma unroll
        for (int j = 0; j < 8; j++) acc[i][j] += a[i] * bv[j];
    }
    __syncthreads();
  }

#pragma unroll
  for (int i = 0; i < 8; i++) {
    int m = row0 + ty * 8 + i;
    if (m < M) {
#pragma unroll
      for (int j = 0; j < 8; j++) {
        int n = col0 + tx * 8 + j;
        float val = acc[i][j] + bias[n];
        if (EPI == EPI_QKV) {
          int part = n / (NH * HD);
          int cin = n - part * (NH * HD);
          int head = cin >> 6, d = cin & 63;
          int win = m / NTOK, tok = m - win * NTOK;
          size_t idx = (((size_t)(win * NH + head)) * NTOK + tok) * HD + d;
          (part == 0 ? g_q : part == 1 ? g_k : g_v)[idx] = val;
        } else if (EPI == EPI_PROJ) {
          int win = m / NTOK, tok = m - win * NTOK;
          int bb = win / 25, wr = win % 25, wh = wr / 5, ww = wr % 5;
          int ii = tok / WS, jj = tok - ii * WS;
          int h = wh * WS + ii, w = ww * WS + jj;
          if (h < Hh && w < Ww) {
            size_t o = (((size_t)bb * Hh + h) * Ww + w) * Cc + n;
            g_h[o] = extra[o] + val;          // residual + attn (cropped)
          }
        } else if (EPI == EPI_LIN1) {
          float x = val;
          g_m1[(size_t)m * MLP + n] =
              0.5f * x * (1.f + erff(x * 0.70710678118654752f));
        } else {  // EPI_LIN2
          Cout[(size_t)m * N + n] = g_h[(size_t)m * N + n] + val;
        }
      }
    }
  }
}

// ---------------- windowed attention: one CTA per (window, head) ----------------
constexpr size_t ATTN_SMEM = (size_t)(2 * NTOK * HD + 2 * NREL * HD) * sizeof(float);

__global__ __launch_bounds__(224) void k_attn(const float* __restrict__ rph,
                                              const float* __restrict__ rpw) {
  int hb = blockIdx.x;  // 0..2399
  int win = hb / NH, head = hb - win * NH;
  extern __shared__ float sm[];
  float* ks = sm;
  float* vs = sm + NTOK * HD;
  float* rh = vs + NTOK * HD;
  float* rw = rh + NREL * HD;

  const float* kg = g_k + (size_t)hb * NTOK * HD;
  const float* vg = g_v + (size_t)hb * NTOK * HD;
  int tid = threadIdx.x;
  for (int i = tid; i < NTOK * HD; i += 224) { ks[i] = kg[i]; vs[i] = vg[i]; }
  for (int i = tid; i < NREL * HD; i += 224) { rh[i] = rph[i]; rw[i] = rpw[i]; }
  __syncthreads();
  if (tid >= NTOK) return;  // no further barriers below

  const float* qg = g_q + ((size_t)hb * NTOK + tid) * HD;
  float qr[HD];
#pragma unroll
  for (int d = 0; d < HD; d++) qr[d] = qg[d];

  int qh = tid / WS, qw = tid - qh * WS;
  float bh[WS], bw[WS];
#pragma unroll 1
  for (int kk = 0; kk < WS; kk++) {
    const float* r1 = rh + (qh - kk + WS - 1) * HD;
    const float* r2 = rw + (qw - kk + WS - 1) * HD;
    float a1 = 0.f, a2 = 0.f;
#pragma unroll
    for (int d = 0; d < HD; d++) { a1 += qr[d] * r1[d]; a2 += qr[d] * r2[d]; }
    bh[kk] = a1; bw[kk] = a2;
  }

  float s[NTOK];
  float mx = -1e30f;
#pragma unroll 1
  for (int kh = 0; kh < WS; kh++) {
    float bias_h = bh[kh];
#pragma unroll 1
    for (int kw = 0; kw < WS; kw++) {
      int jj = kh * WS + kw;
      const float4* k4 = (const float4*)(ks + jj * HD);
      float a0 = 0.f, a1 = 0.f, a2 = 0.f, a3 = 0.f;
#pragma unroll
      for (int d4 = 0; d4 < HD / 4; d4++) {
        float4 kv = k4[d4];
        a0 += qr[4 * d4 + 0] * kv.x; a1 += qr[4 * d4 + 1] * kv.y;
        a2 += qr[4 * d4 + 2] * kv.z; a3 += qr[4 * d4 + 3] * kv.w;
      }
      float sc = (a0 + a1 + a2 + a3) * SCALE + bias_h + bw[kw];
      s[jj] = sc;
      mx = fmaxf(mx, sc);
    }
  }

  float sum = 0.f;
#pragma unroll 1
  for (int jj = 0; jj < NTOK; jj++) {
    float e = __expf(s[jj] - mx);
    s[jj] = e; sum += e;
  }
  float inv = 1.f / sum;

  float acc[HD];
#pragma unroll
  for (int d = 0; d < HD; d++) acc[d] = 0.f;
#pragma unroll 1
  for (int jj = 0; jj < NTOK; jj++) {
    float p = s[jj];
    const float4* v4 = (const float4*)(vs + jj * HD);
#pragma unroll
    for (int d4 = 0; d4 < HD / 4; d4++) {
      float4 vv = v4[d4];
      acc[4 * d4 + 0] += p * vv.x; acc[4 * d4 + 1] += p * vv.y;
      acc[4 * d4 + 2] += p * vv.z; acc[4 * d4 + 3] += p * vv.w;
    }
  }

  float* og = g_attnout + ((size_t)win * NTOK + tid) * Cc + head * HD;
#pragma unroll
  for (int d = 0; d < HD; d++) og[d] = acc[d] * inv;
}

// ---------------- launch ----------------
extern "C" void kernel_launch(void* const* d_in, const int* in_sizes, int n_in,
                              void* d_out, int out_size) {
  (void)in_sizes; (void)n_in; (void)out_size;
  const float* hs    = (const float*)d_in[0];
  const float* ln1g  = (const float*)d_in[1];
  const float* ln1b  = (const float*)d_in[2];
  const float* qkvw  = (const float*)d_in[3];
  const float* qkvb  = (const float*)d_in[4];
  const float* projw = (const float*)d_in[5];
  const float* projb = (const float*)d_in[6];
  const float* rph   = (const float*)d_in[7];
  const float* rpw   = (const float*)d_in[8];
  const float* ln2g  = (const float*)d_in[9];
  const float* ln2b  = (const float*)d_in[10];
  const float* l1w   = (const float*)d_in[11];
  const float* l1b   = (const float*)d_in[12];
  const float* l2w   = (const float*)d_in[13];
  const float* l2b   = (const float*)d_in[14];
  float* out = (float*)d_out;

  cudaFuncSetAttribute(k_attn, cudaFuncAttributeMaxDynamicSharedMemorySize,
                       (int)ATTN_SMEM);

  k_ln1<<<M1, 256>>>(hs, ln1g, ln1b);

  k_gemm<EPI_QKV><<<dim3((3 * Cc) / BN, (M1 + BM - 1) / BM), 256>>>(
      qkvw, qkvb, nullptr, nullptr, M1, 3 * Cc, Cc);

  k_attn<<<NWIN * NH, 224, ATTN_SMEM>>>(rph, rpw);

  k_gemm<EPI_PROJ><<<dim3(Cc / BN, (M1 + BM - 1) / BM), 256>>>(
      projw, projb, nullptr, hs, M1, Cc, Cc);

  k_ln2<<<M2, 256>>>(ln2g, ln2b);

  k_gemm<EPI_LIN1><<<dim3(MLP / BN, M2 / BM), 256>>>(
      l1w, l1b, nullptr, nullptr, M2, MLP, Cc);

  k_gemm<EPI_LIN2><<<dim3(Cc / BN, M2 / BM), 256>>>(
      l2w, l2b, out, nullptr, M2, Cc, MLP);
}

// round 3
// speedup vs baseline: 1.9677x; 1.9677x over previous
#include <cuda_runtime.h>
#include <cuda_bf16.h>
#include <math.h>
#include <stdint.h>

// ================= constants =================
namespace {
constexpr int Cc = 768, NH = 12, HD = 64, WS = 14, MLP = 3072;
constexpr int NWIN = 200, NTOK = 196;
constexpr int M1 = NWIN * NTOK;   // 39200
constexpr int M2 = 8 * 64 * 64;   // 32768
constexpr int NREL = 2 * WS - 1;  // 27
constexpr float EPS = 1e-6f, SCALE = 0.125f;

constexpr int BM = 128, BN = 128, BK = 32;
constexpr int ROWB = 80;                 // 32 bf16 = 64B + 16B pad
constexpr int ARR = BM * ROWB;           // 10240 B per array
constexpr int STAGE = 4 * ARR;           // 40960 B (Ah, Al, Bh, Bl)
constexpr int DYN_SMEM = 2 * STAGE;      // 81920 B
}

// ================= device scratch =================
__device__ __align__(16) __nv_bfloat16 g_xln_h[(size_t)M1 * Cc];
__device__ __align__(16) __nv_bfloat16 g_xln_l[(size_t)M1 * Cc];
__device__ __align__(16) float g_q[(size_t)NWIN * NH * NTOK * HD];
__device__ __align__(16) float g_k[(size_t)NWIN * NH * NTOK * HD];
__device__ __align__(16) float g_v[(size_t)NWIN * NH * NTOK * HD];
__device__ __align__(16) __nv_bfloat16 g_attn_h[(size_t)M1 * Cc];
__device__ __align__(16) __nv_bfloat16 g_attn_l[(size_t)M1 * Cc];
__device__ __align__(16) float g_h[(size_t)M2 * Cc];
__device__ __align__(16) __nv_bfloat16 g_x2_h[(size_t)M2 * Cc];
__device__ __align__(16) __nv_bfloat16 g_x2_l[(size_t)M2 * Cc];
__device__ __align__(16) __nv_bfloat16 g_m1_h[(size_t)M2 * MLP];
__device__ __align__(16) __nv_bfloat16 g_m1_l[(size_t)M2 * MLP];
// transposed + split weights: [N][K]
__device__ __align__(16) __nv_bfloat16 g_wq_h[(size_t)3 * Cc * Cc];
__device__ __align__(16) __nv_bfloat16 g_wq_l[(size_t)3 * Cc * Cc];
__device__ __align__(16) __nv_bfloat16 g_wp_h[(size_t)Cc * Cc];
__device__ __align__(16) __nv_bfloat16 g_wp_l[(size_t)Cc * Cc];
__device__ __align__(16) __nv_bfloat16 g_w1_h[(size_t)MLP * Cc];
__device__ __align__(16) __nv_bfloat16 g_w1_l[(size_t)MLP * Cc];
__device__ __align__(16) __nv_bfloat16 g_w2_h[(size_t)Cc * MLP];
__device__ __align__(16) __nv_bfloat16 g_w2_l[(size_t)Cc * MLP];

// ================= helpers =================
__device__ __forceinline__ uint32_t s2u(const void* p) {
  uint32_t a;
  asm("{ .reg .u64 t; cvta.to.shared.u64 t, %1; cvt.u32.u64 %0, t; }"
      : "=r"(a) : "l"(p));
  return a;
}
__device__ __forceinline__ void cpa16(uint32_t dst, const void* src, uint32_t sz) {
  asm volatile("cp.async.cg.shared.global [%0], [%1], 16, %2;"
               :: "r"(dst), "l"(src), "r"(sz) : "memory");
}
#define CP_COMMIT() asm volatile("cp.async.commit_group;" ::: "memory")
#define CP_WAIT1() asm volatile("cp.async.wait_group 1;" ::: "memory")

__device__ __forceinline__ void ldsm_x4(uint32_t* r, uint32_t a) {
  asm volatile("ldmatrix.sync.aligned.m8n8.x4.shared.b16 {%0,%1,%2,%3}, [%4];"
               : "=r"(r[0]), "=r"(r[1]), "=r"(r[2]), "=r"(r[3]) : "r"(a));
}
__device__ __forceinline__ void ldsm_x2(uint32_t* r, uint32_t a) {
  asm volatile("ldmatrix.sync.aligned.m8n8.x2.shared.b16 {%0,%1}, [%2];"
               : "=r"(r[0]), "=r"(r[1]) : "r"(a));
}
__device__ __forceinline__ void mma_bf16(float* d, const uint32_t* a,
                                         const uint32_t* b) {
  asm volatile(
      "mma.sync.aligned.m16n8k16.row.col.f32.bf16.bf16.f32 "
      "{%0,%1,%2,%3},{%4,%5,%6,%7},{%8,%9},{%0,%1,%2,%3};"
      : "+f"(d[0]), "+f"(d[1]), "+f"(d[2]), "+f"(d[3])
      : "r"(a[0]), "r"(a[1]), "r"(a[2]), "r"(a[3]), "r"(b[0]), "r"(b[1]));
}
__device__ __forceinline__ void split2(float x, __nv_bfloat16& h, __nv_bfloat16& l) {
  h = __float2bfloat16(x);
  l = __float2bfloat16(x - __bfloat162float(h));
}

// ================= weight transpose + split =================
template <int W>
__global__ __launch_bounds__(256) void k_wsplit(const float* __restrict__ Wsrc,
                                                int K, int N) {
  __nv_bfloat16 *Th, *Tl;
  if (W == 0) { Th = g_wq_h; Tl = g_wq_l; }
  else if (W == 1) { Th = g_wp_h; Tl = g_wp_l; }
  else if (W == 2) { Th = g_w1_h; Tl = g_w1_l; }
  else { Th = g_w2_h; Tl = g_w2_l; }
  __shared__ float t[32][33];
  int n0 = blockIdx.x * 32, k0 = blockIdx.y * 32;
  int tx = threadIdx.x & 31, ty = threadIdx.x >> 5;
  for (int r = ty; r < 32; r += 8)
    t[r][tx] = Wsrc[(size_t)(k0 + r) * N + n0 + tx];
  __syncthreads();
  for (int r = ty; r < 32; r += 8) {
    float x = t[tx][r];
    size_t o = (size_t)(n0 + r) * K + k0 + tx;
    __nv_bfloat16 h, l; split2(x, h, l);
    Th[o] = h; Tl[o] = l;
  }
}

// ================= layernorm (split bf16 out) =================
__device__ __forceinline__ void ln_compute(const float* __restrict__ xr,
                                           const float* __restrict__ g,
                                           const float* __restrict__ bsh,
                                           __nv_bfloat16* __restrict__ oh,
                                           __nv_bfloat16* __restrict__ ol) {
  float vals[3];
  float s = 0.f, s2 = 0.f;
#pragma unroll
  for (int t = 0; t < 3; t++) {
    float v = xr[threadIdx.x + t * 256];
    vals[t] = v; s += v; s2 += v * v;
  }
#pragma unroll
  for (int off = 16; off > 0; off >>= 1) {
    s += __shfl_down_sync(0xffffffffu, s, off);
    s2 += __shfl_down_sync(0xffffffffu, s2, off);
  }
  __shared__ float rs[8], rq[8];
  __shared__ float s_mu, s_inv;
  int lane = threadIdx.x & 31, warp = threadIdx.x >> 5;
  if (lane == 0) { rs[warp] = s; rq[warp] = s2; }
  __syncthreads();
  if (threadIdx.x == 0) {
    float a = 0.f, b2 = 0.f;
#pragma unroll
    for (int i = 0; i < 8; i++) { a += rs[i]; b2 += rq[i]; }
    float mu = a * (1.f / 768.f);
    float var = b2 * (1.f / 768.f) - mu * mu;
    s_mu = mu; s_inv = rsqrtf(var + EPS);
  }
  __syncthreads();
  float mu = s_mu, inv = s_inv;
#pragma unroll
  for (int t = 0; t < 3; t++) {
    int c = threadIdx.x + t * 256;
    float y = (vals[t] - mu) * inv * g[c] + bsh[c];
    __nv_bfloat16 h, l; split2(y, h, l);
    oh[c] = h; ol[c] = l;
  }
}

__global__ __launch_bounds__(256) void k_ln1(const float* __restrict__ x,
                                             const float* __restrict__ g,
                                             const float* __restrict__ b) {
  int m = blockIdx.x;
  int win = m / NTOK, tok = m - win * NTOK;
  int bb = win / 25, wr = win % 25, wh = wr / 5, ww = wr % 5;
  int i = tok / WS, j = tok - i * WS;
  int h = wh * WS + i, w = ww * WS + j;
  __nv_bfloat16* oh = g_xln_h + (size_t)m * Cc;
  __nv_bfloat16* ol = g_xln_l + (size_t)m * Cc;
  if (h >= 64 || w >= 64) {
    __nv_bfloat16 z = __float2bfloat16(0.f);
    for (int c = threadIdx.x; c < Cc; c += 256) { oh[c] = z; ol[c] = z; }
    return;
  }
  const float* xr = x + (((size_t)bb * 64 + h) * 64 + w) * Cc;
  ln_compute(xr, g, b, oh, ol);
}

__global__ __launch_bounds__(256) void k_ln2(const float* __restrict__ g,
                                             const float* __restrict__ b) {
  int m = blockIdx.x;
  ln_compute(g_h + (size_t)m * Cc, g, b, g_x2_h + (size_t)m * Cc,
             g_x2_l + (size_t)m * Cc);
}

// ================= split-bf16 mma.sync GEMM =================
enum { EPI_QKV = 0, EPI_PROJ = 1, EPI_LIN1 = 2, EPI_LIN2 = 3 };

template <int EPI>
__global__ __launch_bounds__(256, 1) void k_gemm(const float* __restrict__ bias,
                                                 const float* __restrict__ extra,
                                                 float* __restrict__ outp,
                                                 int M, int N, int K) {
  extern __shared__ __align__(128) char dsm[];
  const __nv_bfloat16 *Ah_g, *Al_g, *Bh_g, *Bl_g;
  if (EPI == EPI_QKV) { Ah_g = g_xln_h; Al_g = g_xln_l; Bh_g = g_wq_h; Bl_g = g_wq_l; }
  else if (EPI == EPI_PROJ) { Ah_g = g_attn_h; Al_g = g_attn_l; Bh_g = g_wp_h; Bl_g = g_wp_l; }
  else if (EPI == EPI_LIN1) { Ah_g = g_x2_h; Al_g = g_x2_l; Bh_g = g_w1_h; Bl_g = g_w1_l; }
  else { Ah_g = g_m1_h; Al_g = g_m1_l; Bh_g = g_w2_h; Bl_g = g_w2_l; }

  const int tid = threadIdx.x;
  const int wid = tid >> 5, lane = tid & 31;
  const int wm = wid >> 2, wn = wid & 3;  // warp grid 2 x 4
  const int row0 = blockIdx.y * BM, col0 = blockIdx.x * BN;
  const uint32_t smb = s2u(dsm);
  const int nch = K / BK;

  // load thread mapping: chunk = r*4 + c4 ; thread t covers chunks t, t+256
  const int lr = tid >> 2, lc4 = tid & 3;

  auto load_stage = [&](int c) {
    if (c >= nch) { return; }
    int p = c & 1;
    uint32_t sb = smb + p * STAGE;
    int k0 = c * BK;
#pragma unroll
    for (int i = 0; i < 2; i++) {
      int r = lr + i * 64;
      uint32_t doff = r * ROWB + lc4 * 16;
      int gmA = row0 + r;
      uint32_t szA = (gmA < M) ? 16u : 0u;
      size_t offA = (size_t)gmA * K + k0 + lc4 * 8;
      cpa16(sb + doff, Ah_g + offA, szA);
      cpa16(sb + ARR + doff, Al_g + offA, szA);
      size_t offB = (size_t)(col0 + r) * K + k0 + lc4 * 8;
      cpa16(sb + 2 * ARR + doff, Bh_g + offB, 16u);
      cpa16(sb + 3 * ARR + doff, Bl_g + offB, 16u);
    }
  };

  float acc[4][4][4];
#pragma unroll
  for (int i = 0; i < 4; i++)
#pragma unroll
    for (int j = 0; j < 4; j++)
#pragma unroll
      for (int q = 0; q < 4; q++) acc[i][j][q] = 0.f;

  load_stage(0); CP_COMMIT();
  load_stage(1); CP_COMMIT();

  const int arow = lane & 15, ahalf = lane >> 4;
  const int brow = lane & 7, bhalf = (lane >> 3) & 1;

  for (int c = 0; c < nch; c++) {
    CP_WAIT1();
    __syncthreads();
    uint32_t sb = smb + (c & 1) * STAGE;
#pragma unroll
    for (int ks = 0; ks < 2; ks++) {
      uint32_t ah[4][4], al[4][4], bh[4][2], bl[4][2];
#pragma unroll
      for (int mt = 0; mt < 4; mt++) {
        uint32_t a = sb + (wm * 64 + mt * 16 + arow) * ROWB + ks * 32 + ahalf * 16;
        ldsm_x4(ah[mt], a);
        ldsm_x4(al[mt], a + ARR);
      }
#pragma unroll
      for (int nt = 0; nt < 4; nt++) {
        uint32_t a = sb + 2 * ARR + (wn * 32 + nt * 8 + brow) * ROWB + ks * 32 + bhalf * 16;
        ldsm_x2(bh[nt], a);
        ldsm_x2(bl[nt], a + ARR);
      }
#pragma unroll
      for (int mt = 0; mt < 4; mt++)
#pragma unroll
        for (int nt = 0; nt < 4; nt++) {
          mma_bf16(acc[mt][nt], ah[mt], bh[nt]);
          mma_bf16(acc[mt][nt], al[mt], bh[nt]);
          mma_bf16(acc[mt][nt], ah[mt], bl[nt]);
        }
    }
    __syncthreads();
    load_stage(c + 2); CP_COMMIT();
  }

  // ---------------- epilogue from registers ----------------
  const int er = lane >> 2, ec = (lane & 3) * 2;
#pragma unroll
  for (int mt = 0; mt < 4; mt++) {
#pragma unroll
    for (int h = 0; h < 2; h++) {
      int m = row0 + wm * 64 + mt * 16 + er + h * 8;
      if (m >= M) continue;
#pragma unroll
      for (int nt = 0; nt < 4; nt++) {
        int n = col0 + wn * 32 + nt * 8 + ec;
        float v0 = acc[mt][nt][2 * h] + bias[n];
        float v1 = acc[mt][nt][2 * h + 1] + bias[n + 1];

        if (EPI == EPI_QKV) {
          int win = m / NTOK, tok = m - win * NTOK;
          int part = n / Cc, cin = n - part * Cc;
          int head = cin >> 6, d = cin & 63;
          float* dst = (part == 0 ? g_q : part == 1 ? g_k : g_v) +
                       (((size_t)(win * NH + head)) * NTOK + tok) * HD + d;
          dst[0] = v0; dst[1] = v1;
        } else if (EPI == EPI_PROJ) {
          int win = m / NTOK, tok = m - win * NTOK;
          int bb = win / 25, wr = win % 25, wh = wr / 5, wwi = wr % 5;
          int ii = tok / WS, jj = tok - ii * WS;
          int hh = wh * WS + ii, ww2 = wwi * WS + jj;
          if (hh < 64 && ww2 < 64) {
            size_t o = (((size_t)bb * 64 + hh) * 64 + ww2) * Cc + n;
            float2 r2 = *(const float2*)(extra + o);
            *(float2*)(g_h + o) = make_float2(r2.x + v0, r2.y + v1);
          }
        } else if (EPI == EPI_LIN1) {
          size_t o = (size_t)m * MLP + n;
          float x0 = 0.5f * v0 * (1.f + erff(v0 * 0.70710678118654752f));
          float x1 = 0.5f * v1 * (1.f + erff(v1 * 0.70710678118654752f));
          __nv_bfloat16 h0, l0, h1, l1;
          split2(x0, h0, l0); split2(x1, h1, l1);
          __nv_bfloat162 th = __halves2bfloat162(h0, h1);
          __nv_bfloat162 tl = __halves2bfloat162(l0, l1);
          *(uint32_t*)(g_m1_h + o) = *reinterpret_cast<uint32_t*>(&th);
          *(uint32_t*)(g_m1_l + o) = *reinterpret_cast<uint32_t*>(&tl);
        } else {  // LIN2
          size_t o = (size_t)m * Cc + n;
          float2 r2 = *(const float2*)(g_h + o);
          *(float2*)(outp + o) = make_float2(r2.x + v0, r2.y + v1);
        }
      }
    }
  }
}

// ================= windowed attention (fp32, split output) =================
constexpr size_t ATTN_SMEM =
    (size_t)(2 * NTOK * HD + 2 * NREL * HD) * sizeof(float);

__global__ __launch_bounds__(224) void k_attn(const float* __restrict__ rph,
                                              const float* __restrict__ rpw) {
  int hb = blockIdx.x;
  int win = hb / NH, head = hb - win * NH;
  extern __shared__ float sm[];
  float* ks = sm;
  float* vs = sm + NTOK * HD;
  float* rh = vs + NTOK * HD;
  float* rw = rh + NREL * HD;

  const float* kg = g_k + (size_t)hb * NTOK * HD;
  const float* vg = g_v + (size_t)hb * NTOK * HD;
  int tid = threadIdx.x;
  for (int i = tid; i < NTOK * HD; i += 224) { ks[i] = kg[i]; vs[i] = vg[i]; }
  for (int i = tid; i < NREL * HD; i += 224) { rh[i] = rph[i]; rw[i] = rpw[i]; }
  __syncthreads();
  if (tid >= NTOK) return;

  const float* qg = g_q + ((size_t)hb * NTOK + tid) * HD;
  float qr[HD];
#pragma unroll
  for (int d = 0; d < HD; d++) qr[d] = qg[d];

  int qh = tid / WS, qw = tid - qh * WS;
  float bh[WS], bw[WS];
#pragma unroll 1
  for (int kk = 0; kk < WS; kk++) {
    const float* r1 = rh + (qh - kk + WS - 1) * HD;
    const float* r2 = rw + (qw - kk + WS - 1) * HD;
    float a1 = 0.f, a2 = 0.f;
#pragma unroll
    for (int d = 0; d < HD; d++) { a1 += qr[d] * r1[d]; a2 += qr[d] * r2[d]; }
    bh[kk] = a1; bw[kk] = a2;
  }

  float s[NTOK];
  float mx = -1e30f;
#pragma unroll 1
  for (int kh = 0; kh < WS; kh++) {
    float bias_h = bh[kh];
#pragma unroll 1
    for (int kw = 0; kw < WS; kw++) {
      int jj = kh * WS + kw;
      const float4* k4 = (const float4*)(ks + jj * HD);
      float a0 = 0.f, a1 = 0.f, a2 = 0.f, a3 = 0.f;
#pragma unroll
      for (int d4 = 0; d4 < HD / 4; d4++) {
        float4 kv = k4[d4];
        a0 += qr[4 * d4 + 0] * kv.x; a1 += qr[4 * d4 + 1] * kv.y;
        a2 += qr[4 * d4 + 2] * kv.z; a3 += qr[4 * d4 + 3] * kv.w;
      }
      float sc = (a0 + a1 + a2 + a3) * SCALE + bias_h + bw[kw];
      s[jj] = sc;
      mx = fmaxf(mx, sc);
    }
  }

  float sum = 0.f;
#pragma unroll 1
  for (int jj = 0; jj < NTOK; jj++) {
    float e = __expf(s[jj] - mx);
    s[jj] = e; sum += e;
  }
  float inv = 1.f / sum;

  float acc[HD];
#pragma unroll
  for (int d = 0; d < HD; d++) acc[d] = 0.f;
#pragma unroll 1
  for (int jj = 0; jj < NTOK; jj++) {
    float p = s[jj];
    const float4* v4 = (const float4*)(vs + jj * HD);
#pragma unroll
    for (int d4 = 0; d4 < HD / 4; d4++) {
      float4 vv = v4[d4];
      acc[4 * d4 + 0] += p * vv.x; acc[4 * d4 + 1] += p * vv.y;
      acc[4 * d4 + 2] += p * vv.z; acc[4 * d4 + 3] += p * vv.w;
    }
  }

  size_t ob = ((size_t)win * NTOK + tid) * Cc + head * HD;
#pragma unroll
  for (int d = 0; d < HD; d++) {
    float val = acc[d] * inv;
    __nv_bfloat16 h, l; split2(val, h, l);
    g_attn_h[ob + d] = h; g_attn_l[ob + d] = l;
  }
}

// ================= launch =================
extern "C" void kernel_launch(void* const* d_in, const int* in_sizes, int n_in,
                              void* d_out, int out_size) {
  (void)in_sizes; (void)n_in; (void)out_size;
  const float* hs    = (const float*)d_in[0];
  const float* ln1g  = (const float*)d_in[1];
  const float* ln1b  = (const float*)d_in[2];
  const float* qkvw  = (const float*)d_in[3];
  const float* qkvb  = (const float*)d_in[4];
  const float* projw = (const float*)d_in[5];
  const float* projb = (const float*)d_in[6];
  const float* rph   = (const float*)d_in[7];
  const float* rpw   = (const float*)d_in[8];
  const float* ln2g  = (const float*)d_in[9];
  const float* ln2b  = (const float*)d_in[10];
  const float* l1w   = (const float*)d_in[11];
  const float* l1b   = (const float*)d_in[12];
  const float* l2w   = (const float*)d_in[13];
  const float* l2b   = (const float*)d_in[14];
  float* out = (float*)d_out;

  cudaFuncSetAttribute(k_attn, cudaFuncAttributeMaxDynamicSharedMemorySize,
                       (int)ATTN_SMEM);
  cudaFuncSetAttribute(k_gemm<EPI_QKV>, cudaFuncAttributeMaxDynamicSharedMemorySize, DYN_SMEM);
  cudaFuncSetAttribute(k_gemm<EPI_PROJ>, cudaFuncAttributeMaxDynamicSharedMemorySize, DYN_SMEM);
  cudaFuncSetAttribute(k_gemm<EPI_LIN1>, cudaFuncAttributeMaxDynamicSharedMemorySize, DYN_SMEM);
  cudaFuncSetAttribute(k_gemm<EPI_LIN2>, cudaFuncAttributeMaxDynamicSharedMemorySize, DYN_SMEM);

  // weight transpose + split
  k_wsplit<0><<<dim3(3 * Cc / 32, Cc / 32), 256>>>(qkvw, Cc, 3 * Cc);
  k_wsplit<1><<<dim3(Cc / 32, Cc / 32), 256>>>(projw, Cc, Cc);
  k_wsplit<2><<<dim3(MLP / 32, Cc / 32), 256>>>(l1w, Cc, MLP);
  k_wsplit<3><<<dim3(Cc / 32, MLP / 32), 256>>>(l2w, MLP, Cc);

  k_ln1<<<M1, 256>>>(hs, ln1g, ln1b);

  int mt1 = (M1 + BM - 1) / BM;  // 307
  k_gemm<EPI_QKV><<<dim3(3 * Cc / BN, mt1), 256, DYN_SMEM>>>(
      qkvb, nullptr, nullptr, M1, 3 * Cc, Cc);

  k_attn<<<NWIN * NH, 224, ATTN_SMEM>>>(rph, rpw);

  k_gemm<EPI_PROJ><<<dim3(Cc / BN, mt1), 256, DYN_SMEM>>>(
      projb, hs, nullptr, M1, Cc, Cc);

  k_ln2<<<M2, 256>>>(ln2g, ln2b);

  k_gemm<EPI_LIN1><<<dim3(MLP / BN, M2 / BM), 256, DYN_SMEM>>>(
      l1b, nullptr, nullptr, M2, MLP, Cc);

  k_gemm<EPI_LIN2><<<dim3(Cc / BN, M2 / BM), 256, DYN_SMEM>>>(
      l2b, nullptr, out, M2, Cc, MLP);
}

// round 4
// speedup vs baseline: 3.8525x; 1.9578x over previous
#include <cuda_runtime.h>
#include <cuda_fp16.h>
#include <math.h>
#include <stdint.h>

// ================= constants =================
namespace {
constexpr int Cc = 768, NH = 12, HD = 64, WS = 14, MLP = 3072;
constexpr int NWIN = 200, NTOK = 196;
constexpr int M1 = NWIN * NTOK;   // 39200
constexpr int M2 = 8 * 64 * 64;   // 32768
constexpr int NREL = 2 * WS - 1;  // 27
constexpr float EPS = 1e-6f, SCALE = 0.125f;

constexpr int BM = 128, BN = 128, BK = 64;
constexpr int ROWB = 144;                // 64 fp16 = 128B + 16B pad
constexpr int ARR = BM * ROWB;           // 18432 B per operand array
constexpr int STAGE = 2 * ARR;           // 36864 B (A, B)
constexpr int DYN_SMEM = 2 * STAGE;      // 73728 B (2 stages)
}

// ================= device scratch =================
__device__ __align__(16) __half g_xln[(size_t)M1 * Cc];
__device__ __align__(16) float g_q[(size_t)NWIN * NH * NTOK * HD];
__device__ __align__(16) float g_k[(size_t)NWIN * NH * NTOK * HD];
__device__ __align__(16) float g_v[(size_t)NWIN * NH * NTOK * HD];
__device__ __align__(16) __half g_attn[(size_t)M1 * Cc];
__device__ __align__(16) float g_h[(size_t)M2 * Cc];
__device__ __align__(16) __half g_x2[(size_t)M2 * Cc];
__device__ __align__(16) __half g_m1[(size_t)M2 * MLP];
// transposed weights: [N][K] fp16
__device__ __align__(16) __half g_wq[(size_t)3 * Cc * Cc];
__device__ __align__(16) __half g_wp[(size_t)Cc * Cc];
__device__ __align__(16) __half g_w1[(size_t)MLP * Cc];
__device__ __align__(16) __half g_w2[(size_t)Cc * MLP];

// ================= helpers =================
__device__ __forceinline__ uint32_t s2u(const void* p) {
  uint32_t a;
  asm("{ .reg .u64 t; cvta.to.shared.u64 t, %1; cvt.u32.u64 %0, t; }"
      : "=r"(a) : "l"(p));
  return a;
}
__device__ __forceinline__ void cpa16(uint32_t dst, const void* src, uint32_t sz) {
  asm volatile("cp.async.cg.shared.global [%0], [%1], 16, %2;"
               :: "r"(dst), "l"(src), "r"(sz) : "memory");
}
#define CP_COMMIT() asm volatile("cp.async.commit_group;" ::: "memory")
#define CP_WAIT1() asm volatile("cp.async.wait_group 1;" ::: "memory")

__device__ __forceinline__ void ldsm_x4(uint32_t* r, uint32_t a) {
  asm volatile("ldmatrix.sync.aligned.m8n8.x4.shared.b16 {%0,%1,%2,%3}, [%4];"
               : "=r"(r[0]), "=r"(r[1]), "=r"(r[2]), "=r"(r[3]) : "r"(a));
}
__device__ __forceinline__ void mma_fp16(float* d, const uint32_t* a,
                                         const uint32_t* b) {
  asm volatile(
      "mma.sync.aligned.m16n8k16.row.col.f32.f16.f16.f32 "
      "{%0,%1,%2,%3},{%4,%5,%6,%7},{%8,%9},{%0,%1,%2,%3};"
      : "+f"(d[0]), "+f"(d[1]), "+f"(d[2]), "+f"(d[3])
      : "r"(a[0]), "r"(a[1]), "r"(a[2]), "r"(a[3]), "r"(b[0]), "r"(b[1]));
}

// ================= weight transpose (fp32 -> fp16 [N][K]) =================
template <int W>
__global__ __launch_bounds__(256) void k_wsplit(const float* __restrict__ Wsrc,
                                                int K, int N) {
  __half* T;
  if (W == 0) T = g_wq;
  else if (W == 1) T = g_wp;
  else if (W == 2) T = g_w1;
  else T = g_w2;
  __shared__ float t[32][33];
  int n0 = blockIdx.x * 32, k0 = blockIdx.y * 32;
  int tx = threadIdx.x & 31, ty = threadIdx.x >> 5;
  for (int r = ty; r < 32; r += 8)
    t[r][tx] = Wsrc[(size_t)(k0 + r) * N + n0 + tx];
  __syncthreads();
  for (int r = ty; r < 32; r += 8)
    T[(size_t)(n0 + r) * K + k0 + tx] = __float2half(t[tx][r]);
}

// ================= layernorm (fp16 out) =================
__device__ __forceinline__ void ln_compute(const float* __restrict__ xr,
                                           const float* __restrict__ g,
                                           const float* __restrict__ bsh,
                                           __half* __restrict__ o) {
  float vals[3];
  float s = 0.f, s2 = 0.f;
#pragma unroll
  for (int t = 0; t < 3; t++) {
    float v = xr[threadIdx.x + t * 256];
    vals[t] = v; s += v; s2 += v * v;
  }
#pragma unroll
  for (int off = 16; off > 0; off >>= 1) {
    s += __shfl_down_sync(0xffffffffu, s, off);
    s2 += __shfl_down_sync(0xffffffffu, s2, off);
  }
  __shared__ float rs[8], rq[8];
  __shared__ float s_mu, s_inv;
  int lane = threadIdx.x & 31, warp = threadIdx.x >> 5;
  if (lane == 0) { rs[warp] = s; rq[warp] = s2; }
  __syncthreads();
  if (threadIdx.x == 0) {
    float a = 0.f, b2 = 0.f;
#pragma unroll
    for (int i = 0; i < 8; i++) { a += rs[i]; b2 += rq[i]; }
    float mu = a * (1.f / 768.f);
    float var = b2 * (1.f / 768.f) - mu * mu;
    s_mu = mu; s_inv = rsqrtf(var + EPS);
  }
  __syncthreads();
  float mu = s_mu, inv = s_inv;
#pragma unroll
  for (int t = 0; t < 3; t++) {
    int c = threadIdx.x + t * 256;
    o[c] = __float2half((vals[t] - mu) * inv * g[c] + bsh[c]);
  }
}

__global__ __launch_bounds__(256) void k_ln1(const float* __restrict__ x,
                                             const float* __restrict__ g,
                                             const float* __restrict__ b) {
  int m = blockIdx.x;
  int win = m / NTOK, tok = m - win * NTOK;
  int bb = win / 25, wr = win % 25, wh = wr / 5, ww = wr % 5;
  int i = tok / WS, j = tok - i * WS;
  int h = wh * WS + i, w = ww * WS + j;
  __half* o = g_xln + (size_t)m * Cc;
  if (h >= 64 || w >= 64) {
    __half z = __float2half(0.f);
    for (int c = threadIdx.x; c < Cc; c += 256) o[c] = z;
    return;
  }
  const float* xr = x + (((size_t)bb * 64 + h) * 64 + w) * Cc;
  ln_compute(xr, g, b, o);
}

__global__ __launch_bounds__(256) void k_ln2(const float* __restrict__ g,
                                             const float* __restrict__ b) {
  int m = blockIdx.x;
  ln_compute(g_h + (size_t)m * Cc, g, b, g_x2 + (size_t)m * Cc);
}

// ================= fp16 mma.sync GEMM =================
enum { EPI_QKV = 0, EPI_PROJ = 1, EPI_LIN1 = 2, EPI_LIN2 = 3 };

template <int EPI>
__global__ __launch_bounds__(256, 2) void k_gemm(const float* __restrict__ bias,
                                                 const float* __restrict__ extra,
                                                 float* __restrict__ outp,
                                                 int M, int N, int K) {
  extern __shared__ __align__(128) char dsm[];
  const __half *A_g, *B_g;
  if (EPI == EPI_QKV) { A_g = g_xln; B_g = g_wq; }
  else if (EPI == EPI_PROJ) { A_g = g_attn; B_g = g_wp; }
  else if (EPI == EPI_LIN1) { A_g = g_x2; B_g = g_w1; }
  else { A_g = g_m1; B_g = g_w2; }

  const int tid = threadIdx.x;
  const int wid = tid >> 5, lane = tid & 31;
  const int wm = wid >> 2, wn = wid & 3;  // warp grid 2 x 4, warp tile 64x32
  const int row0 = blockIdx.y * BM, col0 = blockIdx.x * BN;
  const uint32_t smb = s2u(dsm);
  const int nch = K / BK;

  // cp.async mapping: each array 128 rows x 8 chunks of 16B
  const int lr = tid >> 3, lc16 = tid & 7;

  auto load_stage = [&](int c) {
    if (c >= nch) return;
    uint32_t sb = smb + (c & 1) * STAGE;
    int k0 = c * BK;
#pragma unroll
    for (int i = 0; i < 4; i++) {
      int r = lr + i * 32;
      uint32_t doff = r * ROWB + lc16 * 16;
      int gmA = row0 + r;
      uint32_t szA = (gmA < M) ? 16u : 0u;
      cpa16(sb + doff, A_g + (size_t)gmA * K + k0 + lc16 * 8, szA);
      cpa16(sb + ARR + doff, B_g + (size_t)(col0 + r) * K + k0 + lc16 * 8, 16u);
    }
  };

  float acc[4][4][4];
#pragma unroll
  for (int i = 0; i < 4; i++)
#pragma unroll
    for (int j = 0; j < 4; j++)
#pragma unroll
      for (int q = 0; q < 4; q++) acc[i][j][q] = 0.f;

  load_stage(0); CP_COMMIT();
  load_stage(1); CP_COMMIT();

  const int arow = lane & 15, ahalf = lane >> 4;
  // B x4: lane->matrix: mat = lane>>3; mat 0,1 = nt even tile (khalf 0,1);
  // mat 2,3 = nt odd tile (khalf 0,1)
  const int bl8 = lane & 7;
  const int bmat = lane >> 3;
  const int bnt_off = (bmat >> 1) * 8;
  const int bhalf = bmat & 1;

  for (int c = 0; c < nch; c++) {
    CP_WAIT1();
    __syncthreads();
    uint32_t sb = smb + (c & 1) * STAGE;
#pragma unroll
    for (int ks = 0; ks < 4; ks++) {
      uint32_t ah[4][4], bq[2][4];
#pragma unroll
      for (int mt = 0; mt < 4; mt++)
        ldsm_x4(ah[mt],
                sb + (wm * 64 + mt * 16 + arow) * ROWB + ks * 32 + ahalf * 16);
#pragma unroll
      for (int np = 0; np < 2; np++)
        ldsm_x4(bq[np], sb + ARR +
                            (wn * 32 + np * 16 + bnt_off + bl8) * ROWB +
                            ks * 32 + bhalf * 16);
#pragma unroll
      for (int mt = 0; mt < 4; mt++)
#pragma unroll
        for (int nt = 0; nt < 4; nt++)
          mma_fp16(acc[mt][nt], ah[mt], &bq[nt >> 1][(nt & 1) * 2]);
    }
    __syncthreads();
    load_stage(c + 2); CP_COMMIT();
  }

  // ---------------- epilogue from registers ----------------
  const int er = lane >> 2, ec = (lane & 3) * 2;
#pragma unroll
  for (int mt = 0; mt < 4; mt++) {
#pragma unroll
    for (int h = 0; h < 2; h++) {
      int m = row0 + wm * 64 + mt * 16 + er + h * 8;
      if (m >= M) continue;
#pragma unroll
      for (int nt = 0; nt < 4; nt++) {
        int n = col0 + wn * 32 + nt * 8 + ec;
        float v0 = acc[mt][nt][2 * h] + bias[n];
        float v1 = acc[mt][nt][2 * h + 1] + bias[n + 1];

        if (EPI == EPI_QKV) {
          int win = m / NTOK, tok = m - win * NTOK;
          int part = n / Cc, cin = n - part * Cc;
          int head = cin >> 6, d = cin & 63;
          float* dst = (part == 0 ? g_q : part == 1 ? g_k : g_v) +
                       (((size_t)(win * NH + head)) * NTOK + tok) * HD + d;
          dst[0] = v0; dst[1] = v1;
        } else if (EPI == EPI_PROJ) {
          int win = m / NTOK, tok = m - win * NTOK;
          int bb = win / 25, wr = win % 25, wh = wr / 5, wwi = wr % 5;
          int ii = tok / WS, jj = tok - ii * WS;
          int hh = wh * WS + ii, ww2 = wwi * WS + jj;
          if (hh < 64 && ww2 < 64) {
            size_t o = (((size_t)bb * 64 + hh) * 64 + ww2) * Cc + n;
            float2 r2 = *(const float2*)(extra + o);
            *(float2*)(g_h + o) = make_float2(r2.x + v0, r2.y + v1);
          }
        } else if (EPI == EPI_LIN1) {
          size_t o = (size_t)m * MLP + n;
          float x0 = 0.5f * v0 * (1.f + erff(v0 * 0.70710678118654752f));
          float x1 = 0.5f * v1 * (1.f + erff(v1 * 0.70710678118654752f));
          __half2 p = __floats2half2_rn(x0, x1);
          *(uint32_t*)(g_m1 + o) = *reinterpret_cast<uint32_t*>(&p);
        } else {  // LIN2
          size_t o = (size_t)m * Cc + n;
          float2 r2 = *(const float2*)(g_h + o);
          *(float2*)(outp + o) = make_float2(r2.x + v0, r2.y + v1);
        }
      }
    }
  }
}

// ================= windowed attention (fp32, fp16 output) =================
constexpr size_t ATTN_SMEM =
    (size_t)(2 * NTOK * HD + 2 * NREL * HD) * sizeof(float);

__global__ __launch_bounds__(224) void k_attn(const float* __restrict__ rph,
                                              const float* __restrict__ rpw) {
  int hb = blockIdx.x;
  int win = hb / NH, head = hb - win * NH;
  extern __shared__ float sm[];
  float* ks = sm;
  float* vs = sm + NTOK * HD;
  float* rh = vs + NTOK * HD;
  float* rw = rh + NREL * HD;

  const float* kg = g_k + (size_t)hb * NTOK * HD;
  const float* vg = g_v + (size_t)hb * NTOK * HD;
  int tid = threadIdx.x;
  for (int i = tid; i < NTOK * HD; i += 224) { ks[i] = kg[i]; vs[i] = vg[i]; }
  for (int i = tid; i < NREL * HD; i += 224) { rh[i] = rph[i]; rw[i] = rpw[i]; }
  __syncthreads();
  if (tid >= NTOK) return;

  const float* qg = g_q + ((size_t)hb * NTOK + tid) * HD;
  float qr[HD];
#pragma unroll
  for (int d = 0; d < HD; d++) qr[d] = qg[d];

  int qh = tid / WS, qw = tid - qh * WS;
  float bh[WS], bw[WS];
#pragma unroll 1
  for (int kk = 0; kk < WS; kk++) {
    const float* r1 = rh + (qh - kk + WS - 1) * HD;
    const float* r2 = rw + (qw - kk + WS - 1) * HD;
    float a1 = 0.f, a2 = 0.f;
#pragma unroll
    for (int d = 0; d < HD; d++) { a1 += qr[d] * r1[d]; a2 += qr[d] * r2[d]; }
    bh[kk] = a1; bw[kk] = a2;
  }

  float s[NTOK];
  float mx = -1e30f;
#pragma unroll 1
  for (int kh = 0; kh < WS; kh++) {
    float bias_h = bh[kh];
#pragma unroll 1
    for (int kw = 0; kw < WS; kw++) {
      int jj = kh * WS + kw;
      const float4* k4 = (const float4*)(ks + jj * HD);
      float a0 = 0.f, a1 = 0.f, a2 = 0.f, a3 = 0.f;
#pragma unroll
      for (int d4 = 0; d4 < HD / 4; d4++) {
        float4 kv = k4[d4];
        a0 += qr[4 * d4 + 0] * kv.x; a1 += qr[4 * d4 + 1] * kv.y;
        a2 += qr[4 * d4 + 2] * kv.z; a3 += qr[4 * d4 + 3] * kv.w;
      }
      float sc = (a0 + a1 + a2 + a3) * SCALE + bias_h + bw[kw];
      s[jj] = sc;
      mx = fmaxf(mx, sc);
    }
  }

  float sum = 0.f;
#pragma unroll 1
  for (int jj = 0; jj < NTOK; jj++) {
    float e = __expf(s[jj] - mx);
    s[jj] = e; sum += e;
  }
  float inv = 1.f / sum;

  float acc[HD];
#pragma unroll
  for (int d = 0; d < HD; d++) acc[d] = 0.f;
#pragma unroll 1
  for (int jj = 0; jj < NTOK; jj++) {
    float p = s[jj];
    const float4* v4 = (const float4*)(vs + jj * HD);
#pragma unroll
    for (int d4 = 0; d4 < HD / 4; d4++) {
      float4 vv = v4[d4];
      acc[4 * d4 + 0] += p * vv.x; acc[4 * d4 + 1] += p * vv.y;
      acc[4 * d4 + 2] += p * vv.z; acc[4 * d4 + 3] += p * vv.w;
    }
  }

  size_t ob = ((size_t)win * NTOK + tid) * Cc + head * HD;
#pragma unroll
  for (int d = 0; d < HD; d++) g_attn[ob + d] = __float2half(acc[d] * inv);
}

// ================= launch =================
extern "C" void kernel_launch(void* const* d_in, const int* in_sizes, int n_in,
                              void* d_out, int out_size) {
  (void)in_sizes; (void)n_in; (void)out_size;
  const float* hs    = (const float*)d_in[0];
  const float* ln1g  = (const float*)d_in[1];
  const float* ln1b  = (const float*)d_in[2];
  const float* qkvw  = (const float*)d_in[3];
  const float* qkvb  = (const float*)d_in[4];
  const float* projw = (const float*)d_in[5];
  const float* projb = (const float*)d_in[6];
  const float* rph   = (const float*)d_in[7];
  const float* rpw   = (const float*)d_in[8];
  const float* ln2g  = (const float*)d_in[9];
  const float* ln2b  = (const float*)d_in[10];
  const float* l1w   = (const float*)d_in[11];
  const float* l1b   = (const float*)d_in[12];
  const float* l2w   = (const float*)d_in[13];
  const float* l2b   = (const float*)d_in[14];
  float* out = (float*)d_out;

  cudaFuncSetAttribute(k_attn, cudaFuncAttributeMaxDynamicSharedMemorySize,
                       (int)ATTN_SMEM);
  cudaFuncSetAttribute(k_gemm<EPI_QKV>, cudaFuncAttributeMaxDynamicSharedMemorySize, DYN_SMEM);
  cudaFuncSetAttribute(k_gemm<EPI_PROJ>, cudaFuncAttributeMaxDynamicSharedMemorySize, DYN_SMEM);
  cudaFuncSetAttribute(k_gemm<EPI_LIN1>, cudaFuncAttributeMaxDynamicSharedMemorySize, DYN_SMEM);
  cudaFuncSetAttribute(k_gemm<EPI_LIN2>, cudaFuncAttributeMaxDynamicSharedMemorySize, DYN_SMEM);

  k_wsplit<0><<<dim3(3 * Cc / 32, Cc / 32), 256>>>(qkvw, Cc, 3 * Cc);
  k_wsplit<1><<<dim3(Cc / 32, Cc / 32), 256>>>(projw, Cc, Cc);
  k_wsplit<2><<<dim3(MLP / 32, Cc / 32), 256>>>(l1w, Cc, MLP);
  k_wsplit<3><<<dim3(Cc / 32, MLP / 32), 256>>>(l2w, MLP, Cc);

  k_ln1<<<M1, 256>>>(hs, ln1g, ln1b);

  int mt1 = (M1 + BM - 1) / BM;  // 307
  k_gemm<EPI_QKV><<<dim3(3 * Cc / BN, mt1), 256, DYN_SMEM>>>(
      qkvb, nullptr, nullptr, M1, 3 * Cc, Cc);

  k_attn<<<NWIN * NH, 224, ATTN_SMEM>>>(rph, rpw);

  k_gemm<EPI_PROJ><<<dim3(Cc / BN, mt1), 256, DYN_SMEM>>>(
      projb, hs, nullptr, M1, Cc, Cc);

  k_ln2<<<M2, 256>>>(ln2g, ln2b);

  k_gemm<EPI_LIN1><<<dim3(MLP / BN, M2 / BM), 256, DYN_SMEM>>>(
      l1b, nullptr, nullptr, M2, MLP, Cc);

  k_gemm<EPI_LIN2><<<dim3(Cc / BN, M2 / BM), 256, DYN_SMEM>>>(
      l2b, nullptr, out, M2, Cc, MLP);
}

// round 5
// speedup vs baseline: 4.3457x; 1.1280x over previous
#include <cuda_runtime.h>
#include <cuda_fp16.h>
#include <math.h>
#include <stdint.h>

// ================= constants =================
namespace {
constexpr int Cc = 768, NH = 12, HD = 64, WS = 14, MLP = 3072;
constexpr int NWIN = 200, NTOK = 196;
constexpr int M1 = NWIN * NTOK;   // 39200
constexpr int M2 = 8 * 64 * 64;   // 32768
constexpr float EPS = 1e-6f, SCALE = 0.125f;

constexpr int BM = 128, BN = 128, BK = 64;
constexpr int ROWB = 144;                // 64 fp16 = 128B + 16B pad
constexpr int ARR = BM * ROWB;           // 18432 B per operand array
constexpr int STAGE = 2 * ARR;           // 36864 B (A, B)
constexpr int DYN_SMEM = 2 * STAGE;      // 73728 B (2 stages)

// attention smem layout (bytes)
constexpr int SQ_OFF = 0;                       // 208 x 144
constexpr int SK_OFF = 29952;                   // 224 x 144
constexpr int SVT_OFF = SK_OFF + 224 * 144;     // 64 x 464 (V^T)
constexpr int VROWB = 464;
constexpr int BH_OFF = SVT_OFF + 64 * VROWB;    // 196x14 f32
constexpr int BW_OFF = BH_OFF + 196 * 14 * 4;
constexpr int ATTN_SMEM = BW_OFF + 196 * 14 * 4;  // 113856
}

// ================= device scratch =================
__device__ __align__(16) __half g_xln[(size_t)M1 * Cc];
__device__ __align__(16) __half g_q[(size_t)NWIN * NH * NTOK * HD];
__device__ __align__(16) __half g_k[(size_t)NWIN * NH * NTOK * HD];
__device__ __align__(16) __half g_v[(size_t)NWIN * NH * NTOK * HD];
__device__ __align__(16) __half g_attn[(size_t)M1 * Cc];
__device__ __align__(16) float g_h[(size_t)M2 * Cc];
__device__ __align__(16) __half g_x2[(size_t)M2 * Cc];
__device__ __align__(16) __half g_m1[(size_t)M2 * MLP];
__device__ __align__(16) __half g_wq[(size_t)3 * Cc * Cc];
__device__ __align__(16) __half g_wp[(size_t)Cc * Cc];
__device__ __align__(16) __half g_w1[(size_t)MLP * Cc];
__device__ __align__(16) __half g_w2[(size_t)Cc * MLP];

// ================= helpers =================
__device__ __forceinline__ uint32_t s2u(const void* p) {
  uint32_t a;
  asm("{ .reg .u64 t; cvta.to.shared.u64 t, %1; cvt.u32.u64 %0, t; }"
      : "=r"(a) : "l"(p));
  return a;
}
__device__ __forceinline__ void cpa16(uint32_t dst, const void* src, uint32_t sz) {
  asm volatile("cp.async.cg.shared.global [%0], [%1], 16, %2;"
               :: "r"(dst), "l"(src), "r"(sz) : "memory");
}
#define CP_COMMIT() asm volatile("cp.async.commit_group;" ::: "memory")
#define CP_WAIT1() asm volatile("cp.async.wait_group 1;" ::: "memory")

__device__ __forceinline__ void ldsm_x4(uint32_t* r, uint32_t a) {
  asm volatile("ldmatrix.sync.aligned.m8n8.x4.shared.b16 {%0,%1,%2,%3}, [%4];"
               : "=r"(r[0]), "=r"(r[1]), "=r"(r[2]), "=r"(r[3]) : "r"(a));
}
__device__ __forceinline__ void mma_fp16(float* d, const uint32_t* a,
                                         const uint32_t* b) {
  asm volatile(
      "mma.sync.aligned.m16n8k16.row.col.f32.f16.f16.f32 "
      "{%0,%1,%2,%3},{%4,%5,%6,%7},{%8,%9},{%0,%1,%2,%3};"
      : "+f"(d[0]), "+f"(d[1]), "+f"(d[2]), "+f"(d[3])
      : "r"(a[0]), "r"(a[1]), "r"(a[2]), "r"(a[3]), "r"(b[0]), "r"(b[1]));
}
// FMA-only expf (no MUFU): exp(x) = 2^(x*log2e), deg-5 poly on [-0.5,0.5]
__device__ __forceinline__ float expf_fast(float x) {
  float y = fmaxf(x * 1.4426950408889634f, -126.f);
  float t = y + 12582912.f;
  int i = __float_as_int(t) - 0x4B400000;
  float f = y - (t - 12582912.f);
  float p = 0.0013333558f;
  p = fmaf(p, f, 0.0096181291f);
  p = fmaf(p, f, 0.0555041087f);
  p = fmaf(p, f, 0.2402265070f);
  p = fmaf(p, f, 0.6931471806f);
  p = fmaf(p, f, 1.0f);
  return __int_as_float(__float_as_int(p) + (i << 23));
}

// ================= weight transpose (fp32 -> fp16 [N][K]) =================
template <int W>
__global__ __launch_bounds__(256) void k_wsplit(const float* __restrict__ Wsrc,
                                                int K, int N) {
  __half* T;
  if (W == 0) T = g_wq;
  else if (W == 1) T = g_wp;
  else if (W == 2) T = g_w1;
  else T = g_w2;
  __shared__ float t[32][33];
  int n0 = blockIdx.x * 32, k0 = blockIdx.y * 32;
  int tx = threadIdx.x & 31, ty = threadIdx.x >> 5;
  for (int r = ty; r < 32; r += 8)
    t[r][tx] = Wsrc[(size_t)(k0 + r) * N + n0 + tx];
  __syncthreads();
  for (int r = ty; r < 32; r += 8)
    T[(size_t)(n0 + r) * K + k0 + tx] = __float2half(t[tx][r]);
}

// ================= layernorm (fp16 out) =================
__device__ __forceinline__ void ln_compute(const float* __restrict__ xr,
                                           const float* __restrict__ g,
                                           const float* __restrict__ bsh,
                                           __half* __restrict__ o) {
  float vals[3];
  float s = 0.f, s2 = 0.f;
#pragma unroll
  for (int t = 0; t < 3; t++) {
    float v = xr[threadIdx.x + t * 256];
    vals[t] = v; s += v; s2 += v * v;
  }
#pragma unroll
  for (int off = 16; off > 0; off >>= 1) {
    s += __shfl_down_sync(0xffffffffu, s, off);
    s2 += __shfl_down_sync(0xffffffffu, s2, off);
  }
  __shared__ float rs[8], rq[8];
  __shared__ float s_mu, s_inv;
  int lane = threadIdx.x & 31, warp = threadIdx.x >> 5;
  if (lane == 0) { rs[warp] = s; rq[warp] = s2; }
  __syncthreads();
  if (threadIdx.x == 0) {
    float a = 0.f, b2 = 0.f;
#pragma unroll
    for (int i = 0; i < 8; i++) { a += rs[i]; b2 += rq[i]; }
    float mu = a * (1.f / 768.f);
    float var = b2 * (1.f / 768.f) - mu * mu;
    s_mu = mu; s_inv = rsqrtf(var + EPS);
  }
  __syncthreads();
  float mu = s_mu, inv = s_inv;
#pragma unroll
  for (int t = 0; t < 3; t++) {
    int c = threadIdx.x + t * 256;
    o[c] = __float2half((vals[t] - mu) * inv * g[c] + bsh[c]);
  }
}

__global__ __launch_bounds__(256) void k_ln1(const float* __restrict__ x,
                                             const float* __restrict__ g,
                                             const float* __restrict__ b) {
  int m = blockIdx.x;
  int win = m / NTOK, tok = m - win * NTOK;
  int bb = win / 25, wr = win % 25, wh = wr / 5, ww = wr % 5;
  int i = tok / WS, j = tok - i * WS;
  int h = wh * WS + i, w = ww * WS + j;
  __half* o = g_xln + (size_t)m * Cc;
  if (h >= 64 || w >= 64) {
    __half z = __float2half(0.f);
    for (int c = threadIdx.x; c < Cc; c += 256) o[c] = z;
    return;
  }
  const float* xr = x + (((size_t)bb * 64 + h) * 64 + w) * Cc;
  ln_compute(xr, g, b, o);
}

__global__ __launch_bounds__(256) void k_ln2(const float* __restrict__ g,
                                             const float* __restrict__ b) {
  int m = blockIdx.x;
  ln_compute(g_h + (size_t)m * Cc, g, b, g_x2 + (size_t)m * Cc);
}

// ================= fp16 mma.sync GEMM =================
enum { EPI_QKV = 0, EPI_PROJ = 1, EPI_LIN1 = 2, EPI_LIN2 = 3 };

template <int EPI>
__global__ __launch_bounds__(256, 2) void k_gemm(const float* __restrict__ bias,
                                                 const float* __restrict__ extra,
                                                 float* __restrict__ outp,
                                                 int M, int N, int K) {
  extern __shared__ __align__(128) char dsm[];
  const __half *A_g, *B_g;
  if (EPI == EPI_QKV) { A_g = g_xln; B_g = g_wq; }
  else if (EPI == EPI_PROJ) { A_g = g_attn; B_g = g_wp; }
  else if (EPI == EPI_LIN1) { A_g = g_x2; B_g = g_w1; }
  else { A_g = g_m1; B_g = g_w2; }

  const int tid = threadIdx.x;
  const int wid = tid >> 5, lane = tid & 31;
  const int wm = wid >> 2, wn = wid & 3;
  const int row0 = blockIdx.y * BM, col0 = blockIdx.x * BN;
  const uint32_t smb = s2u(dsm);
  const int nch = K / BK;

  const int lr = tid >> 3, lc16 = tid & 7;

  auto load_stage = [&](int c) {
    if (c >= nch) return;
    uint32_t sb = smb + (c & 1) * STAGE;
    int k0 = c * BK;
#pragma unroll
    for (int i = 0; i < 4; i++) {
      int r = lr + i * 32;
      uint32_t doff = r * ROWB + lc16 * 16;
      int gmA = row0 + r;
      uint32_t szA = (gmA < M) ? 16u : 0u;
      cpa16(sb + doff, A_g + (size_t)gmA * K + k0 + lc16 * 8, szA);
      cpa16(sb + ARR + doff, B_g + (size_t)(col0 + r) * K + k0 + lc16 * 8, 16u);
    }
  };

  float acc[4][4][4];
#pragma unroll
  for (int i = 0; i < 4; i++)
#pragma unroll
    for (int j = 0; j < 4; j++)
#pragma unroll
      for (int q = 0; q < 4; q++) acc[i][j][q] = 0.f;

  load_stage(0); CP_COMMIT();
  load_stage(1); CP_COMMIT();

  const int arow = lane & 15, ahalf = lane >> 4;
  const int bl8 = lane & 7;
  const int bmat = lane >> 3;
  const int bnt_off = (bmat >> 1) * 8;
  const int bhalf = bmat & 1;

  for (int c = 0; c < nch; c++) {
    CP_WAIT1();
    __syncthreads();
    uint32_t sb = smb + (c & 1) * STAGE;
#pragma unroll
    for (int ks = 0; ks < 4; ks++) {
      uint32_t ah[4][4], bq[2][4];
#pragma unroll
      for (int mt = 0; mt < 4; mt++)
        ldsm_x4(ah[mt],
                sb + (wm * 64 + mt * 16 + arow) * ROWB + ks * 32 + ahalf * 16);
#pragma unroll
      for (int np = 0; np < 2; np++)
        ldsm_x4(bq[np], sb + ARR +
                            (wn * 32 + np * 16 + bnt_off + bl8) * ROWB +
                            ks * 32 + bhalf * 16);
#pragma unroll
      for (int mt = 0; mt < 4; mt++)
#pragma unroll
        for (int nt = 0; nt < 4; nt++)
          mma_fp16(acc[mt][nt], ah[mt], &bq[nt >> 1][(nt & 1) * 2]);
    }
    __syncthreads();
    load_stage(c + 2); CP_COMMIT();
  }

  const int er = lane >> 2, ec = (lane & 3) * 2;
#pragma unroll
  for (int mt = 0; mt < 4; mt++) {
#pragma unroll
    for (int h = 0; h < 2; h++) {
      int m = row0 + wm * 64 + mt * 16 + er + h * 8;
      if (m >= M) continue;
#pragma unroll
      for (int nt = 0; nt < 4; nt++) {
        int n = col0 + wn * 32 + nt * 8 + ec;
        float v0 = acc[mt][nt][2 * h] + bias[n];
        float v1 = acc[mt][nt][2 * h + 1] + bias[n + 1];

        if (EPI == EPI_QKV) {
          int win = m / NTOK, tok = m - win * NTOK;
          int part = n / Cc, cin = n - part * Cc;
          int head = cin >> 6, d = cin & 63;
          __half* dst = (part == 0 ? g_q : part == 1 ? g_k : g_v) +
                        (((size_t)(win * NH + head)) * NTOK + tok) * HD + d;
          __half2 p = __floats2half2_rn(v0, v1);
          *(uint32_t*)dst = *reinterpret_cast<uint32_t*>(&p);
        } else if (EPI == EPI_PROJ) {
          int win = m / NTOK, tok = m - win * NTOK;
          int bb = win / 25, wr = win % 25, wh = wr / 5, wwi = wr % 5;
          int ii = tok / WS, jj = tok - ii * WS;
          int hh = wh * WS + ii, ww2 = wwi * WS + jj;
          if (hh < 64 && ww2 < 64) {
            size_t o = (((size_t)bb * 64 + hh) * 64 + ww2) * Cc + n;
            float2 r2 = *(const float2*)(extra + o);
            *(float2*)(g_h + o) = make_float2(r2.x + v0, r2.y + v1);
          }
        } else if (EPI == EPI_LIN1) {
          size_t o = (size_t)m * MLP + n;
          float x0 = 0.5f * v0 * (1.f + erff(v0 * 0.70710678118654752f));
          float x1 = 0.5f * v1 * (1.f + erff(v1 * 0.70710678118654752f));
          __half2 p = __floats2half2_rn(x0, x1);
          *(uint32_t*)(g_m1 + o) = *reinterpret_cast<uint32_t*>(&p);
        } else {
          size_t o = (size_t)m * Cc + n;
          float2 r2 = *(const float2*)(g_h + o);
          *(float2*)(outp + o) = make_float2(r2.x + v0, r2.y + v1);
        }
      }
    }
  }
}

// ================= flash attention (fp16 mma) =================
// one CTA per (window, head); 256 threads (8 warps)
__global__ __launch_bounds__(256, 2) void k_attn(const float* __restrict__ rph,
                                                 const float* __restrict__ rpw) {
  extern __shared__ __align__(128) char asm_[];
  const int hb = blockIdx.x;
  const int win = hb / NH, head = hb - win * NH;
  const int tid = threadIdx.x;
  const int wid = tid >> 5, lane = tid & 31;
  const uint32_t smb = s2u(asm_);

  // ---- zero whole smem (covers all pad rows/cols) ----
  for (int i = tid * 16; i < ATTN_SMEM; i += 256 * 16)
    *(uint4*)(asm_ + i) = make_uint4(0, 0, 0, 0);
  __syncthreads();

  // ---- load Q, K (196 x 64 fp16) and V^T ----
  const __half* qg = g_q + (size_t)hb * NTOK * HD;
  const __half* kg = g_k + (size_t)hb * NTOK * HD;
  const __half* vg = g_v + (size_t)hb * NTOK * HD;
  for (int idx = tid; idx < NTOK * 8; idx += 256) {
    int r = idx >> 3, c = (idx & 7) * 8;
    uint4 v = *(const uint4*)(qg + r * HD + c);
    *(uint4*)(asm_ + SQ_OFF + r * 144 + c * 2) = v;
    v = *(const uint4*)(kg + r * HD + c);
    *(uint4*)(asm_ + SK_OFF + r * 144 + c * 2) = v;
    // V transpose: 8 halves (d = c..c+7) scattered to rows of Vt
    const __half* vr = vg + r * HD + c;
#pragma unroll
    for (int u = 0; u < 8; u++)
      *(__half*)(asm_ + SVT_OFF + (c + u) * VROWB + r * 2) = vr[u];
  }
  __syncthreads();

  // ---- rel-pos bias tables: bh[196][14], bw[196][14] ----
  for (int t = tid; t < 2 * NTOK * WS; t += 256) {
    int is_w = t >= NTOK * WS;
    int tt = is_w ? t - NTOK * WS : t;
    int i = tt / WS, kk = tt - (tt / WS) * WS;
    int coord = (is_w ? (i % WS) : (i / WS)) - kk + WS - 1;
    const float* tbl = (is_w ? rpw : rph) + coord * HD;
    const __half* qrow = (const __half*)(asm_ + SQ_OFF + i * 144);
    float a = 0.f;
#pragma unroll
    for (int d = 0; d < HD; d++) a += __half2float(qrow[d]) * tbl[d];
    *(float*)(asm_ + (is_w ? BW_OFF : BH_OFF) + (i * WS + kk) * 4) = a;
  }
  __syncthreads();

  const int bl8 = lane & 7;
  const int bmat = lane >> 3;
  const int bnt_off = (bmat >> 1) * 8;
  const int bhalf = bmat & 1;
  const int arow = lane & 15, ahalf = lane >> 4;
  const int er = lane >> 2, ec = (lane & 3) * 2;
  const float* bhp = (const float*)(asm_ + BH_OFF);
  const float* bwp = (const float*)(asm_ + BW_OFF);

  // 13 m-tiles; warp w handles tiles w and w+8
#pragma unroll 1
  for (int pass = 0; pass < 2; pass++) {
    int mt = wid + pass * 8;
    if (mt > 12) continue;
    int r0 = mt * 16 + er, r1 = r0 + 8;

    uint32_t aq[4][4];
#pragma unroll
    for (int kf = 0; kf < 4; kf++)
      ldsm_x4(aq[kf], smb + SQ_OFF + (mt * 16 + arow) * 144 + kf * 32 + ahalf * 16);

    float m0 = -1e30f, m1 = -1e30f, l0 = 0.f, l1 = 0.f;
    float acc[8][4];
#pragma unroll
    for (int i = 0; i < 8; i++)
#pragma unroll
      for (int q = 0; q < 4; q++) acc[i][q] = 0.f;

#pragma unroll 1
    for (int blk = 0; blk < 4; blk++) {
      const int j0 = blk * 64;
      const int nnt = (blk == 3) ? 4 : 8;     // n8 tiles this block
      const int nkf = (blk == 3) ? 2 : 4;     // k16 frags for PV
      float s[8][4];
#pragma unroll
      for (int i = 0; i < 8; i++)
#pragma unroll
        for (int q = 0; q < 4; q++) s[i][q] = 0.f;

      // S = Q K^T
#pragma unroll
      for (int nt2 = 0; nt2 < 4; nt2++) {
        if (nt2 * 2 >= nnt) break;
#pragma unroll
        for (int kf = 0; kf < 4; kf++) {
          uint32_t bq[4];
          ldsm_x4(bq, smb + SK_OFF + (j0 + nt2 * 16 + bnt_off + bl8) * 144 +
                          kf * 32 + bhalf * 16);
          mma_fp16(s[nt2 * 2], aq[kf], bq);
          mma_fp16(s[nt2 * 2 + 1], aq[kf], bq + 2);
        }
      }

      // scale + rel-pos bias + mask
#pragma unroll
      for (int nt = 0; nt < 8; nt++) {
        if (nt >= nnt) break;
        int jc0 = j0 + nt * 8 + ec, jc1 = jc0 + 1;
        int jd0 = (jc0 * 586) >> 13, jm0 = jc0 - jd0 * 14;
        int jd1 = (jc1 * 586) >> 13, jm1 = jc1 - jd1 * 14;
        float b00 = (r0 < NTOK) ? bhp[r0 * 14 + jd0] + bwp[r0 * 14 + jm0] : 0.f;
        float b01 = (r0 < NTOK) ? bhp[r0 * 14 + jd1] + bwp[r0 * 14 + jm1] : 0.f;
        float b10 = (r1 < NTOK) ? bhp[r1 * 14 + jd0] + bwp[r1 * 14 + jm0] : 0.f;
        float b11 = (r1 < NTOK) ? bhp[r1 * 14 + jd1] + bwp[r1 * 14 + jm1] : 0.f;
        s[nt][0] = (jc0 < NTOK) ? s[nt][0] * SCALE + b00 : -1e30f;
        s[nt][1] = (jc1 < NTOK) ? s[nt][1] * SCALE + b01 : -1e30f;
        s[nt][2] = (jc0 < NTOK) ? s[nt][2] * SCALE + b10 : -1e30f;
        s[nt][3] = (jc1 < NTOK) ? s[nt][3] * SCALE + b11 : -1e30f;
      }

      // row max (over this block)
      float bm0 = -1e30f, bm1 = -1e30f;
#pragma unroll
      for (int nt = 0; nt < 8; nt++) {
        if (nt >= nnt) break;
        bm0 = fmaxf(bm0, fmaxf(s[nt][0], s[nt][1]));
        bm1 = fmaxf(bm1, fmaxf(s[nt][2], s[nt][3]));
      }
      bm0 = fmaxf(bm0, __shfl_xor_sync(0xffffffffu, bm0, 1));
      bm0 = fmaxf(bm0, __shfl_xor_sync(0xffffffffu, bm0, 2));
      bm1 = fmaxf(bm1, __shfl_xor_sync(0xffffffffu, bm1, 1));
      bm1 = fmaxf(bm1, __shfl_xor_sync(0xffffffffu, bm1, 2));

      float nm0 = fmaxf(m0, bm0), nm1 = fmaxf(m1, bm1);
      float al0 = expf_fast(m0 - nm0), al1 = expf_fast(m1 - nm1);
      m0 = nm0; m1 = nm1;
#pragma unroll
      for (int i = 0; i < 8; i++) {
        acc[i][0] *= al0; acc[i][1] *= al0;
        acc[i][2] *= al1; acc[i][3] *= al1;
      }
      float ps0 = 0.f, ps1 = 0.f;
#pragma unroll
      for (int nt = 0; nt < 8; nt++) {
        if (nt >= nnt) break;
        s[nt][0] = expf_fast(s[nt][0] - nm0);
        s[nt][1] = expf_fast(s[nt][1] - nm0);
        s[nt][2] = expf_fast(s[nt][2] - nm1);
        s[nt][3] = expf_fast(s[nt][3] - nm1);
        ps0 += s[nt][0] + s[nt][1];
        ps1 += s[nt][2] + s[nt][3];
      }
      ps0 += __shfl_xor_sync(0xffffffffu, ps0, 1);
      ps0 += __shfl_xor_sync(0xffffffffu, ps0, 2);
      ps1 += __shfl_xor_sync(0xffffffffu, ps1, 1);
      ps1 += __shfl_xor_sync(0xffffffffu, ps1, 2);
      l0 = l0 * al0 + ps0;
      l1 = l1 * al1 + ps1;

      // pack P to fp16 A-frags
      uint32_t pa[4][4];
#pragma unroll
      for (int kf = 0; kf < 4; kf++) {
        if (kf >= nkf) break;
        __half2 h0 = __floats2half2_rn(s[2 * kf][0], s[2 * kf][1]);
        __half2 h1 = __floats2half2_rn(s[2 * kf][2], s[2 * kf][3]);
        __half2 h2 = __floats2half2_rn(s[2 * kf + 1][0], s[2 * kf + 1][1]);
        __half2 h3 = __floats2half2_rn(s[2 * kf + 1][2], s[2 * kf + 1][3]);
        pa[kf][0] = *reinterpret_cast<uint32_t*>(&h0);
        pa[kf][1] = *reinterpret_cast<uint32_t*>(&h1);
        pa[kf][2] = *reinterpret_cast<uint32_t*>(&h2);
        pa[kf][3] = *reinterpret_cast<uint32_t*>(&h3);
      }

      // acc += P V
#pragma unroll
      for (int dp = 0; dp < 4; dp++) {
#pragma unroll
        for (int kf = 0; kf < 4; kf++) {
          if (kf >= nkf) break;
          uint32_t bv[4];
          ldsm_x4(bv, smb + SVT_OFF + (dp * 16 + bnt_off + bl8) * VROWB +
                          j0 * 2 + kf * 32 + bhalf * 16);
          mma_fp16(acc[dp * 2], pa[kf], bv);
          mma_fp16(acc[dp * 2 + 1], pa[kf], bv + 2);
        }
      }
    }

    // ---- write output (fp16) ----
    float inv0 = 1.f / l0, inv1 = 1.f / l1;
    __half* ob = g_attn + (size_t)win * NTOK * Cc + head * HD;
#pragma unroll
    for (int dt = 0; dt < 8; dt++) {
      int d = dt * 8 + ec;
      if (r0 < NTOK) {
        __half2 p = __floats2half2_rn(acc[dt][0] * inv0, acc[dt][1] * inv0);
        *(uint32_t*)(ob + (size_t)r0 * Cc + d) = *reinterpret_cast<uint32_t*>(&p);
      }
      if (r1 < NTOK) {
        __half2 p = __floats2half2_rn(acc[dt][2] * inv1, acc[dt][3] * inv1);
        *(uint32_t*)(ob + (size_t)r1 * Cc + d) = *reinterpret_cast<uint32_t*>(&p);
      }
    }
  }
}

// ================= launch =================
extern "C" void kernel_launch(void* const* d_in, const int* in_sizes, int n_in,
                              void* d_out, int out_size) {
  (void)in_sizes; (void)n_in; (void)out_size;
  const float* hs    = (const float*)d_in[0];
  const float* ln1g  = (const float*)d_in[1];
  const float* ln1b  = (const float*)d_in[2];
  const float* qkvw  = (const float*)d_in[3];
  const float* qkvb  = (const float*)d_in[4];
  const float* projw = (const float*)d_in[5];
  const float* projb = (const float*)d_in[6];
  const float* rph   = (const float*)d_in[7];
  const float* rpw   = (const float*)d_in[8];
  const float* ln2g  = (const float*)d_in[9];
  const float* ln2b  = (const float*)d_in[10];
  const float* l1w   = (const float*)d_in[11];
  const float* l1b   = (const float*)d_in[12];
  const float* l2w   = (const float*)d_in[13];
  const float* l2b   = (const float*)d_in[14];
  float* out = (float*)d_out;

  cudaFuncSetAttribute(k_attn, cudaFuncAttributeMaxDynamicSharedMemorySize,
                       ATTN_SMEM);
  cudaFuncSetAttribute(k_gemm<EPI_QKV>, cudaFuncAttributeMaxDynamicSharedMemorySize, DYN_SMEM);
  cudaFuncSetAttribute(k_gemm<EPI_PROJ>, cudaFuncAttributeMaxDynamicSharedMemorySize, DYN_SMEM);
  cudaFuncSetAttribute(k_gemm<EPI_LIN1>, cudaFuncAttributeMaxDynamicSharedMemorySize, DYN_SMEM);
  cudaFuncSetAttribute(k_gemm<EPI_LIN2>, cudaFuncAttributeMaxDynamicSharedMemorySize, DYN_SMEM);

  k_wsplit<0><<<dim3(3 * Cc / 32, Cc / 32), 256>>>(qkvw, Cc, 3 * Cc);
  k_wsplit<1><<<dim3(Cc / 32, Cc / 32), 256>>>(projw, Cc, Cc);
  k_wsplit<2><<<dim3(MLP / 32, Cc / 32), 256>>>(l1w, Cc, MLP);
  k_wsplit<3><<<dim3(Cc / 32, MLP / 32), 256>>>(l2w, MLP, Cc);

  k_ln1<<<M1, 256>>>(hs, ln1g, ln1b);

  int mt1 = (M1 + BM - 1) / BM;  // 307
  k_gemm<EPI_QKV><<<dim3(3 * Cc / BN, mt1), 256, DYN_SMEM>>>(
      qkvb, nullptr, nullptr, M1, 3 * Cc, Cc);

  k_attn<<<NWIN * NH, 256, ATTN_SMEM>>>(rph, rpw);

  k_gemm<EPI_PROJ><<<dim3(Cc / BN, mt1), 256, DYN_SMEM>>>(
      projb, hs, nullptr, M1, Cc, Cc);

  k_ln2<<<M2, 256>>>(ln2g, ln2b);

  k_gemm<EPI_LIN1><<<dim3(MLP / BN, M2 / BM), 256, DYN_SMEM>>>(
      l1b, nullptr, nullptr, M2, MLP, Cc);

  k_gemm<EPI_LIN2><<<dim3(Cc / BN, M2 / BM), 256, DYN_SMEM>>>(
      l2b, nullptr, out, M2, Cc, MLP);
}

// round 6
// speedup vs baseline: 5.3929x; 1.2410x over previous
#include <cuda_runtime.h>
#include <cuda_fp16.h>
#include <math.h>
#include <stdint.h>

// ================= constants =================
namespace {
constexpr int Cc = 768, NH = 12, HD = 64, WS = 14, MLP = 3072;
constexpr int NWIN = 200, NTOK = 196;
constexpr int M1 = NWIN * NTOK;   // 39200
constexpr int M2 = 8 * 64 * 64;   // 32768
constexpr float EPS = 1e-6f, SCALE = 0.125f;

constexpr int BM = 128, BN = 128, BK = 64;
constexpr int ROWB = 144;                // 64 fp16 = 128B + 16B pad
constexpr int ARR = BM * ROWB;           // 18432 B per operand array
constexpr int STAGE = 2 * ARR;           // 36864 B (A, B)
constexpr int DYN_SMEM = 2 * STAGE;      // 73728 B (2 stages)

// attention smem layout (bytes); Q region reused for V
constexpr int AV_OFF = 0;                         // 224 x 144 (Q then V)
constexpr int AK_OFF = 224 * 144;                 // 32256
constexpr int ABH_OFF = AK_OFF + 224 * 144;       // 64512
constexpr int ABW_OFF = ABH_OFF + NTOK * WS * 4;  // +10976
constexpr int ARPH_OFF = ABW_OFF + NTOK * WS * 4;
constexpr int ARPW_OFF = ARPH_OFF + 27 * HD * 4;  // +6912
constexpr int ATTN_SMEM = ARPW_OFF + 27 * HD * 4; // 100288
}

// ================= device scratch =================
__device__ __align__(16) __half g_xln[(size_t)M1 * Cc];
__device__ __align__(16) __half g_q[(size_t)NWIN * NH * NTOK * HD];
__device__ __align__(16) __half g_k[(size_t)NWIN * NH * NTOK * HD];
__device__ __align__(16) __half g_v[(size_t)NWIN * NH * NTOK * HD];
__device__ __align__(16) __half g_attn[(size_t)M1 * Cc];
__device__ __align__(16) float g_h[(size_t)M2 * Cc];
__device__ __align__(16) __half g_x2[(size_t)M2 * Cc];
__device__ __align__(16) __half g_m1[(size_t)M2 * MLP];
__device__ __align__(16) __half g_wq[(size_t)3 * Cc * Cc];
__device__ __align__(16) __half g_wp[(size_t)Cc * Cc];
__device__ __align__(16) __half g_w1[(size_t)MLP * Cc];
__device__ __align__(16) __half g_w2[(size_t)Cc * MLP];

// ================= helpers =================
__device__ __forceinline__ uint32_t s2u(const void* p) {
  uint32_t a;
  asm("{ .reg .u64 t; cvta.to.shared.u64 t, %1; cvt.u32.u64 %0, t; }"
      : "=r"(a) : "l"(p));
  return a;
}
__device__ __forceinline__ void cpa16(uint32_t dst, const void* src, uint32_t sz) {
  asm volatile("cp.async.cg.shared.global [%0], [%1], 16, %2;"
               :: "r"(dst), "l"(src), "r"(sz) : "memory");
}
#define CP_COMMIT() asm volatile("cp.async.commit_group;" ::: "memory")
#define CP_WAIT1() asm volatile("cp.async.wait_group 1;" ::: "memory")

__device__ __forceinline__ void ldsm_x4(uint32_t* r, uint32_t a) {
  asm volatile("ldmatrix.sync.aligned.m8n8.x4.shared.b16 {%0,%1,%2,%3}, [%4];"
               : "=r"(r[0]), "=r"(r[1]), "=r"(r[2]), "=r"(r[3]) : "r"(a));
}
__device__ __forceinline__ void ldsm_x4_t(uint32_t* r, uint32_t a) {
  asm volatile("ldmatrix.sync.aligned.m8n8.x4.trans.shared.b16 {%0,%1,%2,%3}, [%4];"
               : "=r"(r[0]), "=r"(r[1]), "=r"(r[2]), "=r"(r[3]) : "r"(a));
}
__device__ __forceinline__ void mma_fp16(float* d, const uint32_t* a,
                                         const uint32_t* b) {
  asm volatile(
      "mma.sync.aligned.m16n8k16.row.col.f32.f16.f16.f32 "
      "{%0,%1,%2,%3},{%4,%5,%6,%7},{%8,%9},{%0,%1,%2,%3};"
      : "+f"(d[0]), "+f"(d[1]), "+f"(d[2]), "+f"(d[3])
      : "r"(a[0]), "r"(a[1]), "r"(a[2]), "r"(a[3]), "r"(b[0]), "r"(b[1]));
}
// FMA-only expf (no MUFU): exp(x) = 2^(x*log2e), deg-5 poly
__device__ __forceinline__ float expf_fast(float x) {
  float y = fmaxf(x * 1.4426950408889634f, -126.f);
  float t = y + 12582912.f;
  int i = __float_as_int(t) - 0x4B400000;
  float f = y - (t - 12582912.f);
  float p = 0.0013333558f;
  p = fmaf(p, f, 0.0096181291f);
  p = fmaf(p, f, 0.0555041087f);
  p = fmaf(p, f, 0.2402265070f);
  p = fmaf(p, f, 0.6931471806f);
  p = fmaf(p, f, 1.0f);
  return __int_as_float(__float_as_int(p) + (i << 23));
}
// FMA-only reciprocal (bit-hack seed + 3 Newton iters)
__device__ __forceinline__ float rcp_fast(float d) {
  float r = __int_as_float(0x7EF311C3 - __float_as_int(d));
  r = r * fmaf(-d, r, 2.f);
  r = r * fmaf(-d, r, 2.f);
  r = r * fmaf(-d, r, 2.f);
  return r;
}
// exact-erf GELU, FMA only (A&S 7.1.26, |eps|<=1.5e-7)
__device__ __forceinline__ float gelu_f(float x) {
  float z = fabsf(x) * 0.70710678118654752f;
  float t = rcp_fast(fmaf(0.3275911f, z, 1.f));
  float p = 1.061405429f;
  p = fmaf(p, t, -1.453152027f);
  p = fmaf(p, t, 1.421413741f);
  p = fmaf(p, t, -0.284496736f);
  p = fmaf(p, t, 0.254829592f);
  p = p * t;
  float erfz = fmaf(-p, expf_fast(-z * z), 1.f);
  float s = (x >= 0.f) ? erfz : -erfz;
  return 0.5f * x * (1.f + s);
}

// ================= weight transpose (fp32 -> fp16 [N][K]) =================
template <int W>
__global__ __launch_bounds__(256) void k_wsplit(const float* __restrict__ Wsrc,
                                                int K, int N) {
  __half* T;
  if (W == 0) T = g_wq;
  else if (W == 1) T = g_wp;
  else if (W == 2) T = g_w1;
  else T = g_w2;
  __shared__ float t[32][33];
  int n0 = blockIdx.x * 32, k0 = blockIdx.y * 32;
  int tx = threadIdx.x & 31, ty = threadIdx.x >> 5;
  for (int r = ty; r < 32; r += 8)
    t[r][tx] = Wsrc[(size_t)(k0 + r) * N + n0 + tx];
  __syncthreads();
  for (int r = ty; r < 32; r += 8)
    T[(size_t)(n0 + r) * K + k0 + tx] = __float2half(t[tx][r]);
}

// ================= layernorm (fp16 out) =================
__device__ __forceinline__ void ln_compute(const float* __restrict__ xr,
                                           const float* __restrict__ g,
                                           const float* __restrict__ bsh,
                                           __half* __restrict__ o) {
  float vals[3];
  float s = 0.f, s2 = 0.f;
#pragma unroll
  for (int t = 0; t < 3; t++) {
    float v = xr[threadIdx.x + t * 256];
    vals[t] = v; s += v; s2 += v * v;
  }
#pragma unroll
  for (int off = 16; off > 0; off >>= 1) {
    s += __shfl_down_sync(0xffffffffu, s, off);
    s2 += __shfl_down_sync(0xffffffffu, s2, off);
  }
  __shared__ float rs[8], rq[8];
  __shared__ float s_mu, s_inv;
  int lane = threadIdx.x & 31, warp = threadIdx.x >> 5;
  if (lane == 0) { rs[warp] = s; rq[warp] = s2; }
  __syncthreads();
  if (threadIdx.x == 0) {
    float a = 0.f, b2 = 0.f;
#pragma unroll
    for (int i = 0; i < 8; i++) { a += rs[i]; b2 += rq[i]; }
    float mu = a * (1.f / 768.f);
    float var = b2 * (1.f / 768.f) - mu * mu;
    s_mu = mu; s_inv = rsqrtf(var + EPS);
  }
  __syncthreads();
  float mu = s_mu, inv = s_inv;
#pragma unroll
  for (int t = 0; t < 3; t++) {
    int c = threadIdx.x + t * 256;
    o[c] = __float2half((vals[t] - mu) * inv * g[c] + bsh[c]);
  }
}

__global__ __launch_bounds__(256) void k_ln1(const float* __restrict__ x,
                                             const float* __restrict__ g,
                                             const float* __restrict__ b) {
  int m = blockIdx.x;
  int win = m / NTOK, tok = m - win * NTOK;
  int bb = win / 25, wr = win % 25, wh = wr / 5, ww = wr % 5;
  int i = tok / WS, j = tok - i * WS;
  int h = wh * WS + i, w = ww * WS + j;
  __half* o = g_xln + (size_t)m * Cc;
  if (h >= 64 || w >= 64) {
    __half z = __float2half(0.f);
    for (int c = threadIdx.x; c < Cc; c += 256) o[c] = z;
    return;
  }
  const float* xr = x + (((size_t)bb * 64 + h) * 64 + w) * Cc;
  ln_compute(xr, g, b, o);
}

__global__ __launch_bounds__(256) void k_ln2(const float* __restrict__ g,
                                             const float* __restrict__ b) {
  int m = blockIdx.x;
  ln_compute(g_h + (size_t)m * Cc, g, b, g_x2 + (size_t)m * Cc);
}

// ================= fp16 mma.sync GEMM =================
enum { EPI_QKV = 0, EPI_PROJ = 1, EPI_LIN1 = 2, EPI_LIN2 = 3 };

template <int EPI>
__global__ __launch_bounds__(256, 2) void k_gemm(const float* __restrict__ bias,
                                                 const float* __restrict__ extra,
                                                 float* __restrict__ outp,
                                                 int M, int N, int K) {
  extern __shared__ __align__(128) char dsm[];
  const __half *A_g, *B_g;
  if (EPI == EPI_QKV) { A_g = g_xln; B_g = g_wq; }
  else if (EPI == EPI_PROJ) { A_g = g_attn; B_g = g_wp; }
  else if (EPI == EPI_LIN1) { A_g = g_x2; B_g = g_w1; }
  else { A_g = g_m1; B_g = g_w2; }

  const int tid = threadIdx.x;
  const int wid = tid >> 5, lane = tid & 31;
  const int wm = wid >> 2, wn = wid & 3;
  const int row0 = blockIdx.y * BM, col0 = blockIdx.x * BN;
  const uint32_t smb = s2u(dsm);
  const int nch = K / BK;

  const int lr = tid >> 3, lc16 = tid & 7;

  auto load_stage = [&](int c) {
    if (c >= nch) return;
    uint32_t sb = smb + (c & 1) * STAGE;
    int k0 = c * BK;
#pragma unroll
    for (int i = 0; i < 4; i++) {
      int r = lr + i * 32;
      uint32_t doff = r * ROWB + lc16 * 16;
      int gmA = row0 + r;
      uint32_t szA = (gmA < M) ? 16u : 0u;
      cpa16(sb + doff, A_g + (size_t)gmA * K + k0 + lc16 * 8, szA);
      cpa16(sb + ARR + doff, B_g + (size_t)(col0 + r) * K + k0 + lc16 * 8, 16u);
    }
  };

  float acc[4][4][4];
#pragma unroll
  for (int i = 0; i < 4; i++)
#pragma unroll
    for (int j = 0; j < 4; j++)
#pragma unroll
      for (int q = 0; q < 4; q++) acc[i][j][q] = 0.f;

  load_stage(0); CP_COMMIT();
  load_stage(1); CP_COMMIT();

  const int arow = lane & 15, ahalf = lane >> 4;
  const int bl8 = lane & 7;
  const int bmat = lane >> 3;
  const int bnt_off = (bmat >> 1) * 8;
  const int bhalf = bmat & 1;

  for (int c = 0; c < nch; c++) {
    CP_WAIT1();
    __syncthreads();
    uint32_t sb = smb + (c & 1) * STAGE;
#pragma unroll
    for (int ks = 0; ks < 4; ks++) {
      uint32_t ah[4][4], bq[2][4];
#pragma unroll
      for (int mt = 0; mt < 4; mt++)
        ldsm_x4(ah[mt],
                sb + (wm * 64 + mt * 16 + arow) * ROWB + ks * 32 + ahalf * 16);
#pragma unroll
      for (int np = 0; np < 2; np++)
        ldsm_x4(bq[np], sb + ARR +
                            (wn * 32 + np * 16 + bnt_off + bl8) * ROWB +
                            ks * 32 + bhalf * 16);
#pragma unroll
      for (int mt = 0; mt < 4; mt++)
#pragma unroll
        for (int nt = 0; nt < 4; nt++)
          mma_fp16(acc[mt][nt], ah[mt], &bq[nt >> 1][(nt & 1) * 2]);
    }
    __syncthreads();
    load_stage(c + 2); CP_COMMIT();
  }

  const int er = lane >> 2, ec = (lane & 3) * 2;
#pragma unroll
  for (int mt = 0; mt < 4; mt++) {
#pragma unroll
    for (int h = 0; h < 2; h++) {
      int m = row0 + wm * 64 + mt * 16 + er + h * 8;
      if (m >= M) continue;
#pragma unroll
      for (int nt = 0; nt < 4; nt++) {
        int n = col0 + wn * 32 + nt * 8 + ec;
        float v0 = acc[mt][nt][2 * h] + bias[n];
        float v1 = acc[mt][nt][2 * h + 1] + bias[n + 1];

        if (EPI == EPI_QKV) {
          int win = m / NTOK, tok = m - win * NTOK;
          int part = n / Cc, cin = n - part * Cc;
          int head = cin >> 6, d = cin & 63;
          __half* dst = (part == 0 ? g_q : part == 1 ? g_k : g_v) +
                        (((size_t)(win * NH + head)) * NTOK + tok) * HD + d;
          __half2 p = __floats2half2_rn(v0, v1);
          *(uint32_t*)dst = *reinterpret_cast<uint32_t*>(&p);
        } else if (EPI == EPI_PROJ) {
          int win = m / NTOK, tok = m - win * NTOK;
          int bb = win / 25, wr = win % 25, wh = wr / 5, wwi = wr % 5;
          int ii = tok / WS, jj = tok - ii * WS;
          int hh = wh * WS + ii, ww2 = wwi * WS + jj;
          if (hh < 64 && ww2 < 64) {
            size_t o = (((size_t)bb * 64 + hh) * 64 + ww2) * Cc + n;
            float2 r2 = *(const float2*)(extra + o);
            *(float2*)(g_h + o) = make_float2(r2.x + v0, r2.y + v1);
          }
        } else if (EPI == EPI_LIN1) {
          size_t o = (size_t)m * MLP + n;
          __half2 p = __floats2half2_rn(gelu_f(v0), gelu_f(v1));
          *(uint32_t*)(g_m1 + o) = *reinterpret_cast<uint32_t*>(&p);
        } else {
          size_t o = (size_t)m * Cc + n;
          float2 r2 = *(const float2*)(g_h + o);
          *(float2*)(outp + o) = make_float2(r2.x + v0, r2.y + v1);
        }
      }
    }
  }
}

// ================= flash attention (fp16 mma, 512 thr, 1 m-tile/warp) ====
__global__ __launch_bounds__(512) void k_attn(const float* __restrict__ rph,
                                              const float* __restrict__ rpw) {
  extern __shared__ __align__(128) char asm_[];
  const int hb = blockIdx.x;
  const int win = hb / NH, head = hb - win * NH;
  const int tid = threadIdx.x;
  const int wid = tid >> 5, lane = tid & 31;
  const uint32_t smb = s2u(asm_);

  // ---- zero pad rows (196..223) of AV and AK regions ----
  for (int i = tid; i < 2 * 28 * 9; i += 512) {
    int reg = (i < 28 * 9) ? AV_OFF : AK_OFF;
    int ii = (i < 28 * 9) ? i : i - 28 * 9;
    int r = 196 + ii / 9, c16 = ii % 9;
    *(uint4*)(asm_ + reg + r * 144 + c16 * 16) = make_uint4(0, 0, 0, 0);
  }
  // ---- load Q -> AV, K -> AK (196 rows) ----
  const __half* qg = g_q + (size_t)hb * NTOK * HD;
  const __half* kg = g_k + (size_t)hb * NTOK * HD;
  const __half* vg = g_v + (size_t)hb * NTOK * HD;
  for (int idx = tid; idx < NTOK * 8; idx += 512) {
    int r = idx >> 3, c = (idx & 7) * 8;
    *(uint4*)(asm_ + AV_OFF + r * 144 + c * 2) = *(const uint4*)(qg + r * HD + c);
    *(uint4*)(asm_ + AK_OFF + r * 144 + c * 2) = *(const uint4*)(kg + r * HD + c);
  }
  // ---- load rel-pos tables to smem (27*64 f32 each = 432 float4) ----
  for (int idx = tid; idx < 2 * 432; idx += 512) {
    if (idx < 432)
      ((float4*)(asm_ + ARPH_OFF))[idx] = ((const float4*)rph)[idx];
    else
      ((float4*)(asm_ + ARPW_OFF))[idx - 432] = ((const float4*)rpw)[idx - 432];
  }
  __syncthreads();

  // ---- rel-pos bias tables: bh[196][14], bw[196][14] (all from smem) ----
  for (int t = tid; t < 2 * NTOK * WS; t += 512) {
    int is_w = t >= NTOK * WS;
    int tt = is_w ? t - NTOK * WS : t;
    int i = tt / WS, kk = tt - (tt / WS) * WS;
    int coord = (is_w ? (i % WS) : (i / WS)) - kk + WS - 1;
    const float* tbl =
        (const float*)(asm_ + (is_w ? ARPW_OFF : ARPH_OFF) + coord * HD * 4);
    const __half2* q2 = (const __half2*)(asm_ + AV_OFF + i * 144);
    float a = 0.f;
#pragma unroll
    for (int d2 = 0; d2 < HD / 2; d2++) {
      float2 qq = __half22float2(q2[d2]);
      a = fmaf(qq.x, tbl[2 * d2], a);
      a = fmaf(qq.y, tbl[2 * d2 + 1], a);
    }
    *(float*)(asm_ + (is_w ? ABW_OFF : ABH_OFF) + (i * WS + kk) * 4) = a;
  }

  // ---- per-warp Q fragments (before V overwrites Q region) ----
  const int arow = lane & 15, ahalf = lane >> 4;
  const int mt = wid;  // warps 0..12 active
  uint32_t aq[4][4];
  if (mt <= 12) {
#pragma unroll
    for (int kf = 0; kf < 4; kf++)
      ldsm_x4(aq[kf],
              smb + AV_OFF + (mt * 16 + arow) * 144 + kf * 32 + ahalf * 16);
  }
  __syncthreads();

  // ---- overwrite AV region with V (rows 0..195) ----
  for (int idx = tid; idx < NTOK * 8; idx += 512) {
    int r = idx >> 3, c = (idx & 7) * 8;
    *(uint4*)(asm_ + AV_OFF + r * 144 + c * 2) = *(const uint4*)(vg + r * HD + c);
  }
  __syncthreads();

  if (mt > 12) return;

  const int bl8 = lane & 7;
  const int bmat = lane >> 3;
  const int bnt_off = (bmat >> 1) * 8;
  const int bhalf = bmat & 1;
  const int er = lane >> 2, ec = (lane & 3) * 2;
  // V trans-frag lane mapping
  const int vk = (lane & 7) + ((lane >> 3) & 1) * 8;
  const int vn = (lane >> 4) * 8;
  const float* bhp = (const float*)(asm_ + ABH_OFF);
  const float* bwp = (const float*)(asm_ + ABW_OFF);

  int r0 = mt * 16 + er, r1 = r0 + 8;

  float m0 = -1e30f, m1 = -1e30f, l0 = 0.f, l1 = 0.f;
  float acc[8][4];
#pragma unroll
  for (int i = 0; i < 8; i++)
#pragma unroll
    for (int q = 0; q < 4; q++) acc[i][q] = 0.f;

#pragma unroll 1
  for (int blk = 0; blk < 4; blk++) {
    const int j0 = blk * 64;
    const int nnt = (blk == 3) ? 4 : 8;
    const int nkf = (blk == 3) ? 2 : 4;
    float s[8][4];
#pragma unroll
    for (int i = 0; i < 8; i++)
#pragma unroll
      for (int q = 0; q < 4; q++) s[i][q] = 0.f;

    // S = Q K^T
#pragma unroll
    for (int nt2 = 0; nt2 < 4; nt2++) {
      if (nt2 * 2 >= nnt) break;
#pragma unroll
      for (int kf = 0; kf < 4; kf++) {
        uint32_t bq[4];
        ldsm_x4(bq, smb + AK_OFF + (j0 + nt2 * 16 + bnt_off + bl8) * 144 +
                        kf * 32 + bhalf * 16);
        mma_fp16(s[nt2 * 2], aq[kf], bq);
        mma_fp16(s[nt2 * 2 + 1], aq[kf], bq + 2);
      }
    }

    // scale + rel-pos bias + mask
#pragma unroll
    for (int nt = 0; nt < 8; nt++) {
      if (nt >= nnt) break;
      int jc0 = j0 + nt * 8 + ec, jc1 = jc0 + 1;
      int jd0 = (jc0 * 586) >> 13, jm0 = jc0 - jd0 * 14;
      int jd1 = (jc1 * 586) >> 13, jm1 = jc1 - jd1 * 14;
      float b00 = bhp[r0 * 14 + jd0] + bwp[r0 * 14 + jm0];
      float b01 = bhp[r0 * 14 + jd1] + bwp[r0 * 14 + jm1];
      float b10 = (r1 < NTOK) ? bhp[r1 * 14 + jd0] + bwp[r1 * 14 + jm0] : 0.f;
      float b11 = (r1 < NTOK) ? bhp[r1 * 14 + jd1] + bwp[r1 * 14 + jm1] : 0.f;
      s[nt][0] = (jc0 < NTOK) ? s[nt][0] * SCALE + b00 : -1e30f;
      s[nt][1] = (jc1 < NTOK) ? s[nt][1] * SCALE + b01 : -1e30f;
      s[nt][2] = (jc0 < NTOK) ? s[nt][2] * SCALE + b10 : -1e30f;
      s[nt][3] = (jc1 < NTOK) ? s[nt][3] * SCALE + b11 : -1e30f;
    }

    // block row max
    float bm0 = -1e30f, bm1 = -1e30f;
#pragma unroll
    for (int nt = 0; nt < 8; nt++) {
      if (nt >= nnt) break;
      bm0 = fmaxf(bm0, fmaxf(s[nt][0], s[nt][1]));
      bm1 = fmaxf(bm1, fmaxf(s[nt][2], s[nt][3]));
    }
    bm0 = fmaxf(bm0, __shfl_xor_sync(0xffffffffu, bm0, 1));
    bm0 = fmaxf(bm0, __shfl_xor_sync(0xffffffffu, bm0, 2));
    bm1 = fmaxf(bm1, __shfl_xor_sync(0xffffffffu, bm1, 1));
    bm1 = fmaxf(bm1, __shfl_xor_sync(0xffffffffu, bm1, 2));

    float nm0 = fmaxf(m0, bm0), nm1 = fmaxf(m1, bm1);
    float al0 = expf_fast(m0 - nm0), al1 = expf_fast(m1 - nm1);
    m0 = nm0; m1 = nm1;
#pragma unroll
    for (int i = 0; i < 8; i++) {
      acc[i][0] *= al0; acc[i][1] *= al0;
      acc[i][2] *= al1; acc[i][3] *= al1;
    }
    float ps0 = 0.f, ps1 = 0.f;
#pragma unroll
    for (int nt = 0; nt < 8; nt++) {
      if (nt >= nnt) break;
      s[nt][0] = expf_fast(s[nt][0] - nm0);
      s[nt][1] = expf_fast(s[nt][1] - nm0);
      s[nt][2] = expf_fast(s[nt][2] - nm1);
      s[nt][3] = expf_fast(s[nt][3] - nm1);
      ps0 += s[nt][0] + s[nt][1];
      ps1 += s[nt][2] + s[nt][3];
    }
    ps0 += __shfl_xor_sync(0xffffffffu, ps0, 1);
    ps0 += __shfl_xor_sync(0xffffffffu, ps0, 2);
    ps1 += __shfl_xor_sync(0xffffffffu, ps1, 1);
    ps1 += __shfl_xor_sync(0xffffffffu, ps1, 2);
    l0 = l0 * al0 + ps0;
    l1 = l1 * al1 + ps1;

    // pack P to fp16 A-frags
    uint32_t pa[4][4];
#pragma unroll
    for (int kf = 0; kf < 4; kf++) {
      if (kf >= nkf) break;
      __half2 h0 = __floats2half2_rn(s[2 * kf][0], s[2 * kf][1]);
      __half2 h1 = __floats2half2_rn(s[2 * kf][2], s[2 * kf][3]);
      __half2 h2 = __floats2half2_rn(s[2 * kf + 1][0], s[2 * kf + 1][1]);
      __half2 h3 = __floats2half2_rn(s[2 * kf + 1][2], s[2 * kf + 1][3]);
      pa[kf][0] = *reinterpret_cast<uint32_t*>(&h0);
      pa[kf][1] = *reinterpret_cast<uint32_t*>(&h1);
      pa[kf][2] = *reinterpret_cast<uint32_t*>(&h2);
      pa[kf][3] = *reinterpret_cast<uint32_t*>(&h3);
    }

    // acc += P V  (V row-major, B-frags via ldmatrix.trans)
#pragma unroll
    for (int dp = 0; dp < 4; dp++) {
#pragma unroll
      for (int kf = 0; kf < 4; kf++) {
        if (kf >= nkf) break;
        uint32_t bv[4];
        ldsm_x4_t(bv, smb + AV_OFF + (j0 + kf * 16 + vk) * 144 +
                          (dp * 16 + vn) * 2);
        mma_fp16(acc[dp * 2], pa[kf], bv);
        mma_fp16(acc[dp * 2 + 1], pa[kf], bv + 2);
      }
    }
  }

  // ---- write output (fp16) ----
  float inv0 = 1.f / l0, inv1 = 1.f / l1;
  __half* ob = g_attn + (size_t)win * NTOK * Cc + head * HD;
#pragma unroll
  for (int dt = 0; dt < 8; dt++) {
    int d = dt * 8 + ec;
    if (r0 < NTOK) {
      __half2 p = __floats2half2_rn(acc[dt][0] * inv0, acc[dt][1] * inv0);
      *(uint32_t*)(ob + (size_t)r0 * Cc + d) = *reinterpret_cast<uint32_t*>(&p);
    }
    if (r1 < NTOK) {
      __half2 p = __floats2half2_rn(acc[dt][2] * inv1, acc[dt][3] * inv1);
      *(uint32_t*)(ob + (size_t)r1 * Cc + d) = *reinterpret_cast<uint32_t*>(&p);
    }
  }
}

// ================= launch =================
extern "C" void kernel_launch(void* const* d_in, const int* in_sizes, int n_in,
                              void* d_out, int out_size) {
  (void)in_sizes; (void)n_in; (void)out_size;
  const float* hs    = (const float*)d_in[0];
  const float* ln1g  = (const float*)d_in[1];
  const float* ln1b  = (const float*)d_in[2];
  const float* qkvw  = (const float*)d_in[3];
  const float* qkvb  = (const float*)d_in[4];
  const float* projw = (const float*)d_in[5];
  const float* projb = (const float*)d_in[6];
  const float* rph   = (const float*)d_in[7];
  const float* rpw   = (const float*)d_in[8];
  const float* ln2g  = (const float*)d_in[9];
  const float* ln2b  = (const float*)d_in[10];
  const float* l1w   = (const float*)d_in[11];
  const float* l1b   = (const float*)d_in[12];
  const float* l2w   = (const float*)d_in[13];
  const float* l2b   = (const float*)d_in[14];
  float* out = (float*)d_out;

  cudaFuncSetAttribute(k_attn, cudaFuncAttributeMaxDynamicSharedMemorySize,
                       ATTN_SMEM);
  cudaFuncSetAttribute(k_gemm<EPI_QKV>, cudaFuncAttributeMaxDynamicSharedMemorySize, DYN_SMEM);
  cudaFuncSetAttribute(k_gemm<EPI_PROJ>, cudaFuncAttributeMaxDynamicSharedMemorySize, DYN_SMEM);
  cudaFuncSetAttribute(k_gemm<EPI_LIN1>, cudaFuncAttributeMaxDynamicSharedMemorySize, DYN_SMEM);
  cudaFuncSetAttribute(k_gemm<EPI_LIN2>, cudaFuncAttributeMaxDynamicSharedMemorySize, DYN_SMEM);

  k_wsplit<0><<<dim3(3 * Cc / 32, Cc / 32), 256>>>(qkvw, Cc, 3 * Cc);
  k_wsplit<1><<<dim3(Cc / 32, Cc / 32), 256>>>(projw, Cc, Cc);
  k_wsplit<2><<<dim3(MLP / 32, Cc / 32), 256>>>(l1w, Cc, MLP);
  k_wsplit<3><<<dim3(Cc / 32, MLP / 32), 256>>>(l2w, MLP, Cc);

  k_ln1<<<M1, 256>>>(hs, ln1g, ln1b);

  int mt1 = (M1 + BM - 1) / BM;  // 307
  k_gemm<EPI_QKV><<<dim3(3 * Cc / BN, mt1), 256, DYN_SMEM>>>(
      qkvb, nullptr, nullptr, M1, 3 * Cc, Cc);

  k_attn<<<NWIN * NH, 512, ATTN_SMEM>>>(rph, rpw);

  k_gemm<EPI_PROJ><<<dim3(Cc / BN, mt1), 256, DYN_SMEM>>>(
      projb, hs, nullptr, M1, Cc, Cc);

  k_ln2<<<M2, 256>>>(ln2g, ln2b);

  k_gemm<EPI_LIN1><<<dim3(MLP / BN, M2 / BM), 256, DYN_SMEM>>>(
      l1b, nullptr, nullptr, M2, MLP, Cc);

  k_gemm<EPI_LIN2><<<dim3(Cc / BN, M2 / BM), 256, DYN_SMEM>>>(
      l2b, nullptr, out, M2, Cc, MLP);
}